// round 12
// baseline (speedup 1.0000x reference)
#include <cuda_runtime.h>
#include <math.h>
#include <stdint.h>

#define NNB 4
#define CCH 128
#define HHH 96
#define WWW 96
#define HWX 9216
#define HH2 48
#define HW2 2304
#define ROWS 9216
#define CODES 1024
#define GN_EPS_F 1e-5f
#define SLOPE_F 0.2f

// ---------------- scratch ----------------
__device__ float g_bufA[NNB*CCH*HWX];
__device__ float g_bufB[NNB*CCH*HW2];
__device__ float g_z[NNB*CCH*HW2];
__device__ float g_h[NNB*CCH*HWX];
__device__ float g_y[NNB*CCH*HWX];
__device__ float g_e1h[NNB*CCH*96*104];
__device__ float g_e1l[NNB*CCH*96*104];
__device__ float g_dcomb[NNB*256*96*104];
__device__ float g_qpack[NNB*CCH*HH2*52];
__device__ float g_wpack[9*256*128];
__device__ float g_wd0[9*128*128];
__device__ float g_we1h[9*128*128];
__device__ float g_we1l[9*128*128];
__device__ float g_pv[ROWS*24];
__device__ int   g_pi[ROWS*24];
__device__ float g_en2[CODES];
__device__ float g_part[8*32*2];
__device__ float g_stats2[4][8][2];
__device__ float g_losspart[36];
__device__ int   g_idx0[ROWS];
__device__ int   g_counts[CODES];
__device__ int   g_ticket[8];

__device__ __forceinline__ float to_tf32(float v) {
    uint32_t u;
    asm("cvt.rna.tf32.f32 %0, %1;" : "=r"(u) : "f"(v));
    return __uint_as_float(u);
}

__device__ __forceinline__ void mma_tf32(float c[4], float a0, float a1, float a2, float a3,
                                         float b0, float b1) {
    uint32_t A0 = __float_as_uint(a0), A1 = __float_as_uint(a1);
    uint32_t A2 = __float_as_uint(a2), A3 = __float_as_uint(a3);
    uint32_t B0 = __float_as_uint(b0), B1 = __float_as_uint(b1);
    asm volatile(
        "mma.sync.aligned.m16n8k8.row.col.f32.tf32.tf32.f32 "
        "{%0,%1,%2,%3},{%4,%5,%6,%7},{%8,%9},{%0,%1,%2,%3};\n"
        : "+f"(c[0]), "+f"(c[1]), "+f"(c[2]), "+f"(c[3])
        : "r"(A0), "r"(A1), "r"(A2), "r"(A3), "r"(B0), "r"(B1));
}

// ---------------- combined init + weight packing (e1/d0/d1 only) ----------------
__global__ void init_pack_kernel(const float* __restrict__ d1w, const float* __restrict__ d0w,
                                 const float* __restrict__ e1w) {
    int t = blockIdx.x*256 + threadIdx.x;
    if (t < CODES) g_counts[t] = 0;
    if (t < 8) g_ticket[t] = 0;
    if (t < 9*256*128) {
        int co = t & 127, ci = (t >> 7) & 255, tap = t >> 15;
        g_wpack[((size_t)tap*256 + ci)*128 + co] = to_tf32(d1w[((size_t)co*256 + ci)*9 + tap]);
    }
    if (t < 9*128*128) {
        int co = t & 127, ci = (t >> 7) & 127, tap = t >> 14;
        g_wd0[((size_t)tap*128 + ci)*128 + co] = to_tf32(d0w[((size_t)ci*128 + co)*9 + tap]);
        float v = e1w[((size_t)co*128 + ci)*9 + tap];
        float h = to_tf32(v);
        g_we1h[((size_t)tap*128 + ci)*128 + co] = h;
        g_we1l[((size_t)tap*128 + ci)*128 + co] = to_tf32(v - h);
    }
}

// ---------------- e0: conv3x3 s1 p1, 4->128, co-split, raw weights ----------------
__global__ void __launch_bounds__(192) conv_e0_kernel(const float* __restrict__ x,
                                                      const float* __restrict__ w,
                                                      const float* __restrict__ b,
                                                      float* __restrict__ out) {
    int oh0 = blockIdx.x*2, n = blockIdx.y, ch = blockIdx.z*64;
    __shared__ float xs[4][4][98];
    __shared__ float ws[36*64];
    int tid = threadIdx.x;
    for (int j = tid; j < 4*4*98; j += 192) {
        int ci = j/392, r2 = j%392, y = r2/98, xx = r2%98;
        int ih = oh0 - 1 + y, iw = xx - 1;
        float v = 0.f;
        if (ih >= 0 && ih < HHH && iw >= 0 && iw < WWW)
            v = x[((size_t)(n*4 + ci))*HWX + ih*WWW + iw];
        xs[ci][y][xx] = v;
    }
    for (int j = tid; j < 36*64; j += 192) {
        int tap = j >> 6, co = j & 63;
        ws[j] = w[(ch + co)*36 + tap];
    }
    __syncthreads();
    int r = tid/96, ow = tid%96, oh = oh0 + r;
    float iv[36];
    #pragma unroll
    for (int ci = 0; ci < 4; ci++)
        #pragma unroll
        for (int kh = 0; kh < 3; kh++)
            #pragma unroll
            for (int kw = 0; kw < 3; kw++)
                iv[ci*9 + kh*3 + kw] = xs[ci][r + kh][ow + kw];
    for (int co0 = 0; co0 < 64; co0 += 4) {
        float4 acc = *(const float4*)&b[ch + co0];
        #pragma unroll
        for (int tap = 0; tap < 36; tap++) {
            float4 wv = *(const float4*)&ws[tap*64 + co0];
            acc.x += iv[tap]*wv.x; acc.y += iv[tap]*wv.y;
            acc.z += iv[tap]*wv.z; acc.w += iv[tap]*wv.w;
        }
        float* op = out + ((size_t)(n*CCH + ch + co0))*HWX + oh*WWW + ow;
        op[0] = acc.x; op[HWX] = acc.y; op[2*HWX] = acc.z; op[3*HWX] = acc.w;
    }
}

// ---------------- GroupNorm stats: float4 loads + last-block ticket ----------------
__global__ void gn_part_kernel(const float* __restrict__ buf, int hw, int stage) {
    int ng = blockIdx.x, bb = blockIdx.y;
    int n = ng >> 1, g = ng & 1;
    const float4* p4 = (const float4*)(buf + ((size_t)n*CCH + g*64)*hw);
    int len4 = 16*hw;
    float s = 0.f, ss = 0.f;
    for (int i = bb*256 + threadIdx.x; i < len4; i += 32*256) {
        float4 v = p4[i];
        s += (v.x + v.y) + (v.z + v.w);
        ss += v.x*v.x + v.y*v.y + v.z*v.z + v.w*v.w;
    }
    __shared__ float sh[256], sh2[256];
    __shared__ int flag;
    sh[threadIdx.x] = s; sh2[threadIdx.x] = ss; __syncthreads();
    for (int o = 128; o; o >>= 1) {
        if (threadIdx.x < o) { sh[threadIdx.x] += sh[threadIdx.x+o]; sh2[threadIdx.x] += sh2[threadIdx.x+o]; }
        __syncthreads();
    }
    if (threadIdx.x == 0) {
        g_part[(ng*32+bb)*2] = sh[0]; g_part[(ng*32+bb)*2+1] = sh2[0];
        __threadfence();
        int done = atomicAdd(&g_ticket[stage], 1);
        flag = (done == 255);
    }
    __syncthreads();
    if (flag && threadIdx.x < 8) {
        int g2 = threadIdx.x;
        float s2 = 0.f, ss2 = 0.f;
        for (int b2 = 0; b2 < 32; b2++) { s2 += g_part[(g2*32+b2)*2]; ss2 += g_part[(g2*32+b2)*2+1]; }
        float cnt = 64.f * (float)hw;
        float mu  = s2 / cnt;
        float var = ss2 / cnt - mu*mu;
        g_stats2[stage][g2][0] = mu; g_stats2[stage][g2][1] = rsqrtf(var + GN_EPS_F);
    }
}

// ---------------- prep_e1 ----------------
__global__ void __launch_bounds__(256) prep_e1_kernel(const float* __restrict__ in,
                                                      const float* __restrict__ gam,
                                                      const float* __restrict__ bet) {
    int gw = blockIdx.x*8 + (threadIdx.x >> 5);
    int lane = threadIdx.x & 31;
    int ih = gw % 96; int t = gw / 96; int ci = t & 127; int n = t >> 7;
    int ng = n*2 + (ci >> 6);
    float rs = g_stats2[0][ng][1], mu = g_stats2[0][ng][0];
    float A = rs*gam[ci];
    float B = bet[ci] - mu*A;
    const float* src = in + ((size_t)(n*CCH + ci))*HWX + ih*WWW;
    float* dh = g_e1h + (size_t)gw*104;
    float* dl = g_e1l + (size_t)gw*104;
    #pragma unroll
    for (int r = 0; r < 3; r++) {
        int iw = lane + r*32;
        float v = src[iw];
        v = fmaf(v, A, B);
        v = v >= 0.f ? v : SLOPE_F*v;
        float h = to_tf32(v);
        int dst = (iw & 1) ? ((iw+1) >> 1) : (52 + (iw >> 1));
        dh[dst] = h; dl[dst] = to_tf32(v - h);
    }
    if (lane == 0) { dh[0] = 0.f; dl[0] = 0.f; }
}

// ---------------- prep_d ----------------
__global__ void __launch_bounds__(256) prep_d_kernel(const float* __restrict__ in,
                                                     const float* __restrict__ gam,
                                                     const float* __restrict__ bet) {
    int gw = blockIdx.x*8 + (threadIdx.x >> 5);
    int lane = threadIdx.x & 31;
    int ih = gw % 96; int t = gw / 96; int ci = t & 127; int n = t >> 7;
    int ng = n*2 + (ci >> 6);
    float rs = g_stats2[2][ng][1], mu = g_stats2[2][ng][0];
    float A = rs*gam[ci];
    float B = bet[ci] - mu*A;
    const float* src = in + ((size_t)(n*CCH + ci))*HWX + ih*WWW;
    float* dst = g_dcomb + ((size_t)((n*256 + ci)*96 + ih))*104;
    #pragma unroll
    for (int r = 0; r < 3; r++) {
        int iw = lane + r*32;
        float v = src[iw];
        v = fmaf(v, A, B);
        v = v >= 0.f ? v : SLOPE_F*v;
        dst[iw + 1] = to_tf32(v);
    }
    if (lane == 0) dst[0] = 0.f;
    if (lane < 7) dst[97 + lane] = 0.f;
}

// ---------------- prep_q ----------------
__global__ void __launch_bounds__(256) prep_q_kernel(const float* __restrict__ emb) {
    int gw = blockIdx.x*8 + (threadIdx.x >> 5);
    int lane = threadIdx.x & 31;
    int ih = gw % HH2; int t = gw / HH2; int ci = t & 127; int n = t >> 7;
    const int* idx = g_idx0 + n*HW2 + ih*HH2;
    float* dst = g_qpack + (size_t)gw*52;
    dst[lane] = to_tf32(emb[(size_t)idx[lane]*CCH + ci]);
    if (lane < 16) dst[32 + lane] = to_tf32(emb[(size_t)idx[32 + lane]*CCH + ci]);
    if (lane < 4) dst[48 + lane] = 0.f;
}

// ---------------- e1: split-tf32 MMA, pipelined ----------------
#define E1_SMEM_FLOATS (4160+4160+2880+2880)
__global__ void __launch_bounds__(256) conv_e1_mma_kernel(
        const float* __restrict__ bias, float* __restrict__ out) {
    extern __shared__ float smem[];
    float* inh = smem;
    float* inl = smem + 4160;
    float* wsh = smem + 8320;
    float* wsl = smem + 11200;
    int oh0 = blockIdx.x*2, cb = blockIdx.y*32, n = blockIdx.z;
    int tid = threadIdx.x, lane = tid & 31, wid = tid >> 5;
    int row = (wid >> 2) & 1, m0 = ((wid >> 1) & 1)*16, half = wid & 1;
    int grp = lane >> 2, qid = lane & 3;
    float acc[3][4];
    #pragma unroll
    for (int i = 0; i < 3; i++)
        #pragma unroll
        for (int j = 0; j < 4; j++) acc[i][j] = 0.f;

    const float4 zero4 = make_float4(0.f, 0.f, 0.f, 0.f);
    for (int j = tid; j < 8*5*26; j += 256) {
        int ci = j/130, r = j%130, y = r/26, q = r%26;
        int ih = 2*oh0 - 1 + y;
        float4 vh = zero4, vl = zero4;
        if (ih >= 0 && ih < 96) {
            size_t srow = ((size_t)((n*CCH + ci)*96 + ih))*26 + q;
            vh = ((const float4*)g_e1h)[srow];
            vl = ((const float4*)g_e1l)[srow];
        }
        *(float4*)&inh[ci*520 + y*104 + q*4] = vh;
        *(float4*)&inl[ci*520 + y*104 + q*4] = vl;
    }
    {
        int ciw = tid >> 5, cow = tid & 31;
        #pragma unroll
        for (int it = 0; it < 9; it++) {
            size_t src = ((size_t)(it*128 + ciw))*128 + cb + cow;
            int dst = it*320 + ciw*40 + cow;
            wsh[dst] = g_we1h[src];
            wsl[dst] = g_we1l[src];
        }
    }
    __syncthreads();

    for (int c0 = 0; c0 < 128; c0 += 8) {
        float4 ph[5], pl[5];
        float pwh[9], pwl[9];
        bool nx = (c0 < 120);
        if (nx) {
            int cn = c0 + 8;
            #pragma unroll
            for (int it = 0; it < 5; it++) {
                int j = tid + it*256;
                ph[it] = zero4; pl[it] = zero4;
                if (j < 1040) {
                    int ci = j/130, r = j%130, y = r/26, q = r%26;
                    int ih = 2*oh0 - 1 + y;
                    if (ih >= 0 && ih < 96) {
                        size_t srow = ((size_t)((n*CCH + cn+ci)*96 + ih))*26 + q;
                        ph[it] = ((const float4*)g_e1h)[srow];
                        pl[it] = ((const float4*)g_e1l)[srow];
                    }
                }
            }
            int ciw = tid >> 5, cow = tid & 31;
            #pragma unroll
            for (int it = 0; it < 9; it++) {
                size_t src = ((size_t)(it*128 + cn+ciw))*128 + cb + cow;
                pwh[it] = g_we1h[src];
                pwl[it] = g_we1l[src];
            }
        }
        #pragma unroll
        for (int kh = 0; kh < 3; kh++) {
            #pragma unroll
            for (int kw = 0; kw < 3; kw++) {
                int tap = kh*3 + kw;
                int wb = tap*320 + qid*40 + m0 + grp;
                float ah0 = wsh[wb],     ah1 = wsh[wb+8];
                float ah2 = wsh[wb+160], ah3 = wsh[wb+168];
                float al0 = wsl[wb],     al1 = wsl[wb+8];
                float al2 = wsl[wb+160], al3 = wsl[wb+168];
                int bb = qid*520 + (2*row + kh)*104 + (kw & 1)*52 + (kw >> 1) + half*24 + grp;
                #pragma unroll
                for (int nt = 0; nt < 3; nt++) {
                    float bh0 = inh[bb + nt*8], bh1 = inh[bb + 2080 + nt*8];
                    float bl0 = inl[bb + nt*8], bl1 = inl[bb + 2080 + nt*8];
                    mma_tf32(acc[nt], ah0, ah1, ah2, ah3, bh0, bh1);
                    mma_tf32(acc[nt], ah0, ah1, ah2, ah3, bl0, bl1);
                    mma_tf32(acc[nt], al0, al1, al2, al3, bh0, bh1);
                }
            }
        }
        __syncthreads();
        if (nx) {
            #pragma unroll
            for (int it = 0; it < 5; it++) {
                int j = tid + it*256;
                if (j < 1040) {
                    int ci = j/130, r = j%130, y = r/26, q = r%26;
                    *(float4*)&inh[ci*520 + y*104 + q*4] = ph[it];
                    *(float4*)&inl[ci*520 + y*104 + q*4] = pl[it];
                }
            }
            int ciw = tid >> 5, cow = tid & 31;
            #pragma unroll
            for (int it = 0; it < 9; it++) {
                int dst = it*320 + ciw*40 + cow;
                wsh[dst] = pwh[it];
                wsl[dst] = pwl[it];
            }
            __syncthreads();
        }
    }
    int coA = cb + m0 + grp, coB = coA + 8;
    float bA = bias[coA], bB = bias[coB];
    int oh = oh0 + row;
    float* pA = out + ((size_t)(n*CCH + coA))*HW2 + oh*HH2;
    float* pB = out + ((size_t)(n*CCH + coB))*HW2 + oh*HH2;
    #pragma unroll
    for (int nt = 0; nt < 3; nt++) {
        int px = half*24 + nt*8 + 2*qid;
        pA[px]   = acc[nt][0] + bA;
        pA[px+1] = acc[nt][1] + bA;
        pB[px]   = acc[nt][2] + bB;
        pB[px+1] = acc[nt][3] + bB;
    }
}

// ---------------- pv: 1x1 split-tf32 MMA, pipelined ----------------
__global__ void __launch_bounds__(256) pv_mma_kernel(
        const float* __restrict__ in, const float* __restrict__ w,
        const float* __restrict__ bias, const float* __restrict__ gam,
        const float* __restrict__ bet, float* __restrict__ out) {
    __shared__ float inh[16*104], inl[16*104], wh[16*72], wl[16*72];
    __shared__ float As[128], Bs[128];
    int pt = blockIdx.x*96, cb = blockIdx.y*64, n = blockIdx.z;
    int tid = threadIdx.x, lane = tid & 31, wid = tid >> 5;
    int half = wid >> 2, m0 = (wid & 3)*16;
    int grp = lane >> 2, qid = lane & 3;
    if (tid < 128) {
        int ng = n*2 + (tid >> 6);
        float mu = g_stats2[1][ng][0], rs = g_stats2[1][ng][1];
        float gm = gam[tid];
        As[tid] = rs*gm;
        Bs[tid] = bet[tid] - mu*rs*gm;
    }
    __syncthreads();
    float acc[6][4];
    #pragma unroll
    for (int i = 0; i < 6; i++)
        #pragma unroll
        for (int j = 0; j < 4; j++) acc[i][j] = 0.f;

    #pragma unroll
    for (int it = 0; it < 6; it++) {
        int j = tid + it*256;
        int k = j/96, px = j%96;
        float v = in[((size_t)(n*CCH + k))*HW2 + pt + px];
        v = fmaf(v, As[k], Bs[k]);
        v = v >= 0.f ? v : SLOPE_F*v;
        float h = to_tf32(v);
        inh[k*104 + px] = h; inl[k*104 + px] = to_tf32(v - h);
    }
    #pragma unroll
    for (int it = 0; it < 4; it++) {
        int j = tid + it*256;
        int k = j >> 6, co = j & 63;
        float v = w[(size_t)(cb+co)*128 + k];
        float h = to_tf32(v);
        wh[k*72 + co] = h; wl[k*72 + co] = to_tf32(v - h);
    }
    __syncthreads();

    for (int c0 = 0; c0 < 128; c0 += 16) {
        float pin[6], pwv[4];
        bool nx = (c0 < 112);
        if (nx) {
            int cn = c0 + 16;
            #pragma unroll
            for (int it = 0; it < 6; it++) {
                int j = tid + it*256;
                int k = j/96, px = j%96;
                pin[it] = in[((size_t)(n*CCH + cn+k))*HW2 + pt + px];
            }
            #pragma unroll
            for (int it = 0; it < 4; it++) {
                int j = tid + it*256;
                int k = j >> 6, co = j & 63;
                pwv[it] = w[(size_t)(cb+co)*128 + cn + k];
            }
        }
        #pragma unroll
        for (int ks = 0; ks < 2; ks++) {
            int wb = (ks*8 + qid)*72 + m0 + grp;
            float ah0 = wh[wb], ah1 = wh[wb+8], ah2 = wh[wb+288], ah3 = wh[wb+296];
            float al0 = wl[wb], al1 = wl[wb+8], al2 = wl[wb+288], al3 = wl[wb+296];
            int bb = (ks*8 + qid)*104 + half*48 + grp;
            #pragma unroll
            for (int nt = 0; nt < 6; nt++) {
                float bh0 = inh[bb + nt*8], bh1 = inh[bb + 416 + nt*8];
                float bl0 = inl[bb + nt*8], bl1 = inl[bb + 416 + nt*8];
                mma_tf32(acc[nt], ah0, ah1, ah2, ah3, bh0, bh1);
                mma_tf32(acc[nt], ah0, ah1, ah2, ah3, bl0, bl1);
                mma_tf32(acc[nt], al0, al1, al2, al3, bh0, bh1);
            }
        }
        __syncthreads();
        if (nx) {
            int cn = c0 + 16;
            #pragma unroll
            for (int it = 0; it < 6; it++) {
                int j = tid + it*256;
                int k = j/96, px = j%96;
                float v = fmaf(pin[it], As[cn+k], Bs[cn+k]);
                v = v >= 0.f ? v : SLOPE_F*v;
                float h = to_tf32(v);
                inh[k*104 + px] = h; inl[k*104 + px] = to_tf32(v - h);
            }
            #pragma unroll
            for (int it = 0; it < 4; it++) {
                int j = tid + it*256;
                int k = j >> 6, co = j & 63;
                float h = to_tf32(pwv[it]);
                wh[k*72 + co] = h; wl[k*72 + co] = to_tf32(pwv[it] - h);
            }
            __syncthreads();
        }
    }
    int coA = cb + m0 + grp, coB = coA + 8;
    float bA = bias[coA], bB = bias[coB];
    float* pA = out + ((size_t)(n*CCH + coA))*HW2 + pt;
    float* pB = out + ((size_t)(n*CCH + coB))*HW2 + pt;
    #pragma unroll
    for (int nt = 0; nt < 6; nt++) {
        int px = half*48 + nt*8 + 2*qid;
        pA[px]   = acc[nt][0] + bA;
        pA[px+1] = acc[nt][1] + bA;
        pB[px]   = acc[nt][2] + bB;
        pB[px+1] = acc[nt][3] + bB;
    }
}

// ---------------- skip: 1x1 tf32 MMA, pipelined, writes tf32 into g_dcomb ----------------
__global__ void __launch_bounds__(256) skip_mma_kernel(
        const float* __restrict__ in, const float* __restrict__ w,
        const float* __restrict__ bias, const float* __restrict__ gam,
        const float* __restrict__ bet) {
    __shared__ float inh[16*104], wh[16*136];
    __shared__ float As[128], Bs[128];
    int oh = blockIdx.x, n = blockIdx.y;
    int pt = oh*96;
    int tid = threadIdx.x, lane = tid & 31, wid = tid >> 5;
    int m0 = wid*16;
    int grp = lane >> 2, qid = lane & 3;
    if (tid < 128) {
        int ng = n*2 + (tid >> 6);
        float mu = g_stats2[0][ng][0], rs = g_stats2[0][ng][1];
        float gm = gam[tid];
        As[tid] = rs*gm;
        Bs[tid] = bet[tid] - mu*rs*gm;
    }
    for (int j = tid; j < 128*8; j += 256) {
        int co = j >> 3, c = j & 7;
        int col = (c == 0) ? 0 : 96 + c;
        g_dcomb[((size_t)((n*256 + 128 + co)*96 + oh))*104 + col] = 0.f;
    }
    __syncthreads();
    float acc[12][4];
    #pragma unroll
    for (int i = 0; i < 12; i++)
        #pragma unroll
        for (int j = 0; j < 4; j++) acc[i][j] = 0.f;

    #pragma unroll
    for (int it = 0; it < 6; it++) {
        int j = tid + it*256;
        int k = j/96, px = j%96;
        float v = in[((size_t)(n*CCH + k))*HWX + pt + px];
        v = fmaf(v, As[k], Bs[k]);
        v = v >= 0.f ? v : SLOPE_F*v;
        inh[k*104 + px] = to_tf32(v);
    }
    #pragma unroll
    for (int it = 0; it < 8; it++) {
        int j = tid + it*256;
        int k = j & 15, co = j >> 4;
        wh[k*136 + co] = to_tf32(w[(size_t)co*128 + k]);
    }
    __syncthreads();

    for (int c0 = 0; c0 < 128; c0 += 16) {
        float pin[6], pwv[8];
        bool nx = (c0 < 112);
        if (nx) {
            int cn = c0 + 16;
            #pragma unroll
            for (int it = 0; it < 6; it++) {
                int j = tid + it*256;
                int k = j/96, px = j%96;
                pin[it] = in[((size_t)(n*CCH + cn+k))*HWX + pt + px];
            }
            #pragma unroll
            for (int it = 0; it < 8; it++) {
                int j = tid + it*256;
                int k = j & 15, co = j >> 4;
                pwv[it] = w[(size_t)co*128 + cn + k];
            }
        }
        #pragma unroll
        for (int ks = 0; ks < 2; ks++) {
            int wb = (ks*8 + qid)*136 + m0 + grp;
            float a0 = wh[wb], a1 = wh[wb+8], a2 = wh[wb+544], a3 = wh[wb+552];
            int bb = (ks*8 + qid)*104 + grp;
            #pragma unroll
            for (int nt = 0; nt < 12; nt++) {
                float b0 = inh[bb + nt*8], b1 = inh[bb + 416 + nt*8];
                mma_tf32(acc[nt], a0, a1, a2, a3, b0, b1);
            }
        }
        __syncthreads();
        if (nx) {
            int cn = c0 + 16;
            #pragma unroll
            for (int it = 0; it < 6; it++) {
                int j = tid + it*256;
                int k = j/96, px = j%96;
                float v = fmaf(pin[it], As[cn+k], Bs[cn+k]);
                v = v >= 0.f ? v : SLOPE_F*v;
                inh[k*104 + px] = to_tf32(v);
            }
            #pragma unroll
            for (int it = 0; it < 8; it++) {
                int j = tid + it*256;
                int k = j & 15, co = j >> 4;
                wh[k*136 + co] = to_tf32(pwv[it]);
            }
            __syncthreads();
        }
    }
    int coA = m0 + grp, coB = coA + 8;
    float bA = bias[coA], bB = bias[coB];
    float* pA = g_dcomb + ((size_t)((n*256 + 128 + coA)*96 + oh))*104 + 1;
    float* pB = g_dcomb + ((size_t)((n*256 + 128 + coB)*96 + oh))*104 + 1;
    #pragma unroll
    for (int nt = 0; nt < 12; nt++) {
        int px = nt*8 + 2*qid;
        pA[px]   = to_tf32(acc[nt][0] + bA);
        pA[px+1] = to_tf32(acc[nt][1] + bA);
        pB[px]   = to_tf32(acc[nt][2] + bB);
        pB[px+1] = to_tf32(acc[nt][3] + bB);
    }
}

// ---------------- emb norms ----------------
__global__ void enorm_kernel(const float* __restrict__ emb) {
    int wp = (blockIdx.x*256 + threadIdx.x) >> 5;
    int lane = threadIdx.x & 31;
    if (wp >= CODES) return;
    const float* e = emb + (size_t)wp*CCH;
    float s = 0.f;
    for (int d = lane; d < CCH; d += 32) { float v = e[d]; s += v*v; }
    for (int o = 16; o; o >>= 1) s += __shfl_down_sync(0xffffffffu, s, o);
    if (lane == 0) g_en2[wp] = s;
}

// ---------------- top3 insert ----------------
__device__ __forceinline__ void topk_insert(float v, int i,
        float& v0, int& i0, float& v1, int& i1, float& v2, int& i2) {
    bool b2 = (v < v2) || (v == v2 && i < i2);
    if (!b2) return;
    bool b1 = (v < v1) || (v == v1 && i < i1);
    bool b0 = (v < v0) || (v == v0 && i < i0);
    if (b0)      { v2=v1;i2=i1; v1=v0;i1=i0; v0=v;i0=i; }
    else if (b1) { v2=v1;i2=i1; v1=v; i1=i; }
    else         { v2=v; i2=i; }
}

// ---------------- scores: split-tf32 MMA + fused partial top3, pipelined ----------------
__global__ void __launch_bounds__(256) scores_mma_kernel(const float* __restrict__ emb,
                                                         const float* __restrict__ z) {
    __shared__ float zh[16*136], zl[16*136], eh[16*136], el[16*136];
    int r0 = blockIdx.x*128, c0 = blockIdx.y*128;
    int n0 = r0 / HW2, p0 = r0 % HW2;
    int tid = threadIdx.x, lane = tid & 31, wid = tid >> 5;
    int m0 = wid*16;
    int grp = lane >> 2, qid = lane & 3;
    float acc[16][4];
    #pragma unroll
    for (int i = 0; i < 16; i++)
        #pragma unroll
        for (int j = 0; j < 4; j++) acc[i][j] = 0.f;

    #pragma unroll
    for (int it = 0; it < 8; it++) {
        int j = tid + it*256;
        int k = j >> 7, row = j & 127;
        float v = z[((size_t)(n0*CCH + k))*HW2 + p0 + row];
        float h = to_tf32(v);
        zh[k*136 + row] = h; zl[k*136 + row] = to_tf32(v - h);
    }
    #pragma unroll
    for (int it = 0; it < 8; it++) {
        int j = tid + it*256;
        int cd = j >> 4, k = j & 15;
        float v = emb[(size_t)(c0+cd)*CCH + k];
        float h = to_tf32(v);
        eh[k*136 + cd] = h; el[k*136 + cd] = to_tf32(v - h);
    }
    __syncthreads();

    for (int k0 = 0; k0 < 128; k0 += 16) {
        float pz[8], pe[8];
        bool nx = (k0 < 112);
        if (nx) {
            int kn = k0 + 16;
            #pragma unroll
            for (int it = 0; it < 8; it++) {
                int j = tid + it*256;
                int k = j >> 7, row = j & 127;
                pz[it] = z[((size_t)(n0*CCH + kn + k))*HW2 + p0 + row];
            }
            #pragma unroll
            for (int it = 0; it < 8; it++) {
                int j = tid + it*256;
                int cd = j >> 4, k = j & 15;
                pe[it] = emb[(size_t)(c0+cd)*CCH + kn + k];
            }
        }
        #pragma unroll
        for (int ks = 0; ks < 2; ks++) {
            int wb = (ks*8 + qid)*136 + m0 + grp;
            float ah0 = zh[wb], ah1 = zh[wb+8], ah2 = zh[wb+544], ah3 = zh[wb+552];
            float al0 = zl[wb], al1 = zl[wb+8], al2 = zl[wb+544], al3 = zl[wb+552];
            int bb = (ks*8 + qid)*136 + grp;
            #pragma unroll
            for (int nt = 0; nt < 16; nt++) {
                float bh0 = eh[bb + nt*8], bh1 = eh[bb + 544 + nt*8];
                float bl0 = el[bb + nt*8], bl1 = el[bb + 544 + nt*8];
                mma_tf32(acc[nt], ah0, ah1, ah2, ah3, bh0, bh1);
                mma_tf32(acc[nt], ah0, ah1, ah2, ah3, bl0, bl1);
                mma_tf32(acc[nt], al0, al1, al2, al3, bh0, bh1);
            }
        }
        __syncthreads();
        if (nx) {
            #pragma unroll
            for (int it = 0; it < 8; it++) {
                int j = tid + it*256;
                int k = j >> 7, row = j & 127;
                float h = to_tf32(pz[it]);
                zh[k*136 + row] = h; zl[k*136 + row] = to_tf32(pz[it] - h);
            }
            #pragma unroll
            for (int it = 0; it < 8; it++) {
                int j = tid + it*256;
                int cd = j >> 4, k = j & 15;
                float h = to_tf32(pe[it]);
                eh[k*136 + cd] = h; el[k*136 + cd] = to_tf32(pe[it] - h);
            }
            __syncthreads();
        }
    }
    const float FMAXV = 3.402823466e38f;
    float av0 = FMAXV, av1 = FMAXV, av2 = FMAXV;
    float bv0 = FMAXV, bv1 = FMAXV, bv2 = FMAXV;
    int ai0 = 0x7fffffff, ai1 = 0x7fffffff, ai2 = 0x7fffffff;
    int bi0 = 0x7fffffff, bi1 = 0x7fffffff, bi2 = 0x7fffffff;
    #pragma unroll
    for (int nt = 0; nt < 16; nt++) {
        int code = c0 + nt*8 + 2*qid;
        float e2a = g_en2[code], e2b = g_en2[code+1];
        topk_insert(e2a - 2.f*acc[nt][0], code,   av0,ai0,av1,ai1,av2,ai2);
        topk_insert(e2b - 2.f*acc[nt][1], code+1, av0,ai0,av1,ai1,av2,ai2);
        topk_insert(e2a - 2.f*acc[nt][2], code,   bv0,bi0,bv1,bi1,bv2,bi2);
        topk_insert(e2b - 2.f*acc[nt][3], code+1, bv0,bi0,bv1,bi1,bv2,bi2);
    }
    #pragma unroll
    for (int off = 1; off <= 2; off <<= 1) {
        float t0 = __shfl_xor_sync(0xffffffffu, av0, off); int t0i = __shfl_xor_sync(0xffffffffu, ai0, off);
        float t1 = __shfl_xor_sync(0xffffffffu, av1, off); int t1i = __shfl_xor_sync(0xffffffffu, ai1, off);
        float t2 = __shfl_xor_sync(0xffffffffu, av2, off); int t2i = __shfl_xor_sync(0xffffffffu, ai2, off);
        topk_insert(t0, t0i, av0,ai0,av1,ai1,av2,ai2);
        topk_insert(t1, t1i, av0,ai0,av1,ai1,av2,ai2);
        topk_insert(t2, t2i, av0,ai0,av1,ai1,av2,ai2);
        float u0 = __shfl_xor_sync(0xffffffffu, bv0, off); int u0i = __shfl_xor_sync(0xffffffffu, bi0, off);
        float u1 = __shfl_xor_sync(0xffffffffu, bv1, off); int u1i = __shfl_xor_sync(0xffffffffu, bi1, off);
        float u2 = __shfl_xor_sync(0xffffffffu, bv2, off); int u2i = __shfl_xor_sync(0xffffffffu, bi2, off);
        topk_insert(u0, u0i, bv0,bi0,bv1,bi1,bv2,bi2);
        topk_insert(u1, u1i, bv0,bi0,bv1,bi1,bv2,bi2);
        topk_insert(u2, u2i, bv0,bi0,bv1,bi1,bv2,bi2);
    }
    if (qid == 0) {
        int rowA = r0 + m0 + grp;
        int baseA = rowA*24 + blockIdx.y*3;
        g_pv[baseA] = av0; g_pi[baseA] = ai0;
        g_pv[baseA+1] = av1; g_pi[baseA+1] = ai1;
        g_pv[baseA+2] = av2; g_pi[baseA+2] = ai2;
        int baseB = (rowA+8)*24 + blockIdx.y*3;
        g_pv[baseB] = bv0; g_pi[baseB] = bi0;
        g_pv[baseB+1] = bv1; g_pi[baseB+1] = bi1;
        g_pv[baseB+2] = bv2; g_pi[baseB+2] = bi2;
    }
}

// ---------------- top3 merge + counts ----------------
__global__ void top3_merge_kernel() {
    int t = blockIdx.x*256 + threadIdx.x;
    if (t >= ROWS) return;
    float v0 = 3.402823466e38f, v1 = v0, v2 = v0;
    int i0 = 0x7fffffff, i1 = 0x7fffffff, i2 = 0x7fffffff;
    #pragma unroll
    for (int j = 0; j < 24; j++)
        topk_insert(g_pv[t*24+j], g_pi[t*24+j], v0,i0,v1,i1,v2,i2);
    g_idx0[t] = i0;
    atomicAdd(&g_counts[i2], 1);
}

// ---------------- loss ----------------
__global__ void loss_part_kernel(const float* __restrict__ emb, const float* __restrict__ z) {
    int row = blockIdx.x*256 + threadIdx.x;
    int n = row / HW2, p = row % HW2;
    const float* e = emb + (size_t)g_idx0[row]*CCH;
    float s = 0.f;
    for (int d = 0; d < CCH; d++) {
        float zv = z[((size_t)(n*CCH + d))*HW2 + p];
        float df = e[d] - zv; s += df*df;
    }
    __shared__ float sh[256];
    sh[threadIdx.x] = s; __syncthreads();
    for (int o = 128; o; o >>= 1) { if (threadIdx.x < o) sh[threadIdx.x] += sh[threadIdx.x+o]; __syncthreads(); }
    if (threadIdx.x == 0) g_losspart[blockIdx.x] = sh[0];
}

// ---------------- finalize ----------------
__global__ void finalize_kernel(float* out0, float* outp) {
    __shared__ float sh[1024];
    int t = threadIdx.x;
    float p = (float)g_counts[t] / (float)ROWS;
    sh[t] = p * logf(p + 1e-10f);
    __syncthreads();
    for (int o = 512; o; o >>= 1) { if (t < o) sh[t] += sh[t+o]; __syncthreads(); }
    if (t == 0) {
        outp[0] = expf(-sh[0]);
        float s = 0.f;
        for (int bb = 0; bb < 36; bb++) s += g_losspart[bb];
        out0[0] = 0.25f * s / ((float)ROWS * (float)CCH);
    }
}

// ---------------- d0: transpose conv parity streams, pipelined ----------------
#define D0_SMEM_FLOATS (16*168 + 9*16*40)
#define D0_STREAM(tap, cls, ro, sh)                                          \
    {                                                                        \
        int wb = (tap)*640 + (ks*8 + qid)*40 + m0 + grp;                     \
        float a0 = ws[wb],     a1 = ws[wb+8];                                \
        float a2 = ws[wb+160], a3 = ws[wb+168];                              \
        int bb = (ks*8 + qid)*168 + (sub + (ro))*56 + (sh) + half*24 + grp;  \
        _Pragma("unroll")                                                    \
        for (int nt = 0; nt < 3; nt++) {                                     \
            float b0 = inp[bb + nt*8];                                       \
            float b1 = inp[bb + 672 + nt*8];                                 \
            mma_tf32(acc[cls][nt], a0, a1, a2, a3, b0, b1);                  \
        }                                                                    \
    }
__global__ void __launch_bounds__(256) conv_d0_mma_kernel(
        const float* __restrict__ bias, float* __restrict__ out) {
    extern __shared__ float smem[];
    float* inp = smem;
    float* ws  = smem + 16*168;
    int i0 = blockIdx.x*2, cb = blockIdx.y*32, n = blockIdx.z;
    int tid = threadIdx.x, lane = tid & 31, wid = tid >> 5;
    int sub = (wid >> 2) & 1, m0 = ((wid >> 1) & 1)*16, half = wid & 1;
    int grp = lane >> 2, qid = lane & 3;
    float acc[4][3][4];
    #pragma unroll
    for (int c = 0; c < 4; c++)
        #pragma unroll
        for (int i = 0; i < 3; i++)
            #pragma unroll
            for (int j = 0; j < 4; j++) acc[c][i][j] = 0.f;

    const float4 zero4 = make_float4(0.f, 0.f, 0.f, 0.f);
    for (int j = tid; j < 16*3*13; j += 256) {
        int ci = j/39, r = j%39, y = r/13, q = r%13;
        int ih = i0 + y;
        float4 v = zero4;
        if (ih < HH2)
            v = ((const float4*)g_qpack)[((size_t)((n*CCH + ci)*HH2 + ih))*13 + q];
        *(float4*)&inp[ci*168 + y*56 + q*4] = v;
    }
    #pragma unroll
    for (int it = 0; it < 18; it++) {
        int tap = it >> 1;
        int r = ((it & 1) << 8) + tid;
        int ci = r >> 5, co = r & 31;
        ws[tap*640 + ci*40 + co] = g_wd0[((size_t)(tap*128 + ci))*128 + cb + co];
    }
    __syncthreads();

    for (int c0 = 0; c0 < 128; c0 += 16) {
        float4 pv4[3];
        float pw[18];
        bool nx = (c0 < 112);
        if (nx) {
            int cn = c0 + 16;
            #pragma unroll
            for (int it = 0; it < 3; it++) {
                int j = tid + it*256;
                pv4[it] = zero4;
                if (j < 624) {
                    int ci = j/39, r = j%39, y = r/13, q = r%13;
                    int ih = i0 + y;
                    if (ih < HH2)
                        pv4[it] = ((const float4*)g_qpack)[((size_t)((n*CCH + cn+ci)*HH2 + ih))*13 + q];
                }
            }
            #pragma unroll
            for (int it = 0; it < 18; it++) {
                int tap = it >> 1;
                int r = ((it & 1) << 8) + tid;
                int ci = r >> 5, co = r & 31;
                pw[it] = g_wd0[((size_t)(tap*128 + cn+ci))*128 + cb + co];
            }
        }
        #pragma unroll
        for (int ks = 0; ks < 2; ks++) {
            D0_STREAM(4, 0, 0, 0)
            D0_STREAM(3, 1, 0, 1)
            D0_STREAM(5, 1, 0, 0)
            D0_STREAM(1, 2, 1, 0)
            D0_STREAM(7, 2, 0, 0)
            D0_STREAM(0, 3, 1, 1)
            D0_STREAM(2, 3, 1, 0)
            D0_STREAM(6, 3, 0, 1)
            D0_STREAM(8, 3, 0, 0)
        }
        __syncthreads();
        if (nx) {
            #pragma unroll
            for (int it = 0; it < 3; it++) {
                int j = tid + it*256;
                if (j < 624) {
                    int ci = j/39, r = j%39, y = r/13, q = r%13;
                    *(float4*)&inp[ci*168 + y*56 + q*4] = pv4[it];
                }
            }
            #pragma unroll
            for (int it = 0; it < 18; it++) {
                int tap = it >> 1;
                int r = ((it & 1) << 8) + tid;
                int ci = r >> 5, co = r & 31;
                ws[tap*640 + ci*40 + co] = pw[it];
            }
            __syncthreads();
        }
    }
    int i = i0 + sub;
    int coA = cb + m0 + grp, coB = coA + 8;
    float bA = bias[coA], bB = bias[coB];
    float* pA = out + ((size_t)(n*CCH + coA))*HWX + (2*i)*WWW;
    float* pB = out + ((size_t)(n*CCH + coB))*HWX + (2*i)*WWW;
    #pragma unroll
    for (int nt = 0; nt < 3; nt++) {
        int j = half*24 + nt*8 + 2*qid;
        pA[2*j]       = acc[0][nt][0] + bA;  pA[2*j+1]     = acc[1][nt][0] + bA;
        pA[2*j+2]     = acc[0][nt][1] + bA;  pA[2*j+3]     = acc[1][nt][1] + bA;
        pA[WWW+2*j]   = acc[2][nt][0] + bA;  pA[WWW+2*j+1] = acc[3][nt][0] + bA;
        pA[WWW+2*j+2] = acc[2][nt][1] + bA;  pA[WWW+2*j+3] = acc[3][nt][1] + bA;
        pB[2*j]       = acc[0][nt][2] + bB;  pB[2*j+1]     = acc[1][nt][2] + bB;
        pB[2*j+2]     = acc[0][nt][3] + bB;  pB[2*j+3]     = acc[1][nt][3] + bB;
        pB[WWW+2*j]   = acc[2][nt][2] + bB;  pB[WWW+2*j+1] = acc[3][nt][2] + bB;
        pB[WWW+2*j+2] = acc[2][nt][3] + bB;  pB[WWW+2*j+3] = acc[3][nt][3] + bB;
    }
}

// ---------------- d1: tf32 MMA, pipelined ----------------
#define D1_SMEM_FLOATS (16*424 + 9*16*40)
__global__ void __launch_bounds__(256) conv_d1_mma_kernel(
        const float* __restrict__ wpack, const float* __restrict__ bias,
        float* __restrict__ out) {
    extern __shared__ float smem[];
    float* inh = smem;
    float* wsh = smem + 16*424;
    int oh0 = blockIdx.x*2, cb = blockIdx.y*32, n = blockIdx.z;
    int tid = threadIdx.x, lane = tid & 31, wid = tid >> 5;
    int row = (wid >> 2) & 1, m0 = ((wid >> 1) & 1)*16, half = wid & 1;
    int grp = lane >> 2, qid = lane & 3;
    float acc[6][4];
    #pragma unroll
    for (int i = 0; i < 6; i++)
        #pragma unroll
        for (int j = 0; j < 4; j++) acc[i][j] = 0.f;

    const float4 zero4 = make_float4(0.f, 0.f, 0.f, 0.f);
    for (int j = tid; j < 16*4*26; j += 256) {
        int ci = j/104, r = j%104, y = r/26, q = r%26;
        int ih = oh0 - 1 + y;
        float4 v = zero4;
        if (ih >= 0 && ih < 96)
            v = ((const float4*)g_dcomb)[((size_t)((n*256 + ci)*96 + ih))*26 + q];
        *(float4*)&inh[ci*424 + y*104 + q*4] = v;
    }
    #pragma unroll
    for (int it = 0; it < 18; it++) {
        int tap = it >> 1;
        int r = ((it & 1) << 8) + tid;
        int ci = r >> 5, co = r & 31;
        wsh[tap*640 + ci*40 + co] = wpack[((size_t)(tap*256 + ci))*128 + cb + co];
    }
    __syncthreads();

    for (int c0 = 0; c0 < 256; c0 += 16) {
        float4 pv4[7];
        float pw[18];
        bool nx = (c0 < 240);
        if (nx) {
            int cn = c0 + 16;
            #pragma unroll
            for (int it = 0; it < 7; it++) {
                int j = tid + it*256;
                pv4[it] = zero4;
                if (j < 1664) {
                    int ci = j/104, r = j%104, y = r/26, q = r%26;
                    int ih = oh0 - 1 + y;
                    if (ih >= 0 && ih < 96)
                        pv4[it] = ((const float4*)g_dcomb)[((size_t)((n*256 + cn+ci)*96 + ih))*26 + q];
                }
            }
            #pragma unroll
            for (int it = 0; it < 18; it++) {
                int tap = it >> 1;
                int r = ((it & 1) << 8) + tid;
                int ci = r >> 5, co = r & 31;
                pw[it] = wpack[((size_t)(tap*256 + cn+ci))*128 + cb + co];
            }
        }
        #pragma unroll
        for (int kh = 0; kh < 3; kh++) {
            #pragma unroll
            for (int kw = 0; kw < 3; kw++) {
                int tap = kh*3 + kw;
                #pragma unroll
                for (int ks = 0; ks < 2; ks++) {
                    int wb = tap*640 + (ks*8 + qid)*40 + m0 + grp;
                    float a0 = wsh[wb],     a1 = wsh[wb+8];
                    float a2 = wsh[wb+160], a3 = wsh[wb+168];
                    int bb = (ks*8 + qid)*424 + (row + kh)*104 + kw + half*48 + grp;
                    #pragma unroll
                    for (int nt = 0; nt < 6; nt++) {
                        float b0 = inh[bb + nt*8];
                        float b1 = inh[bb + 1696 + nt*8];
                        mma_tf32(acc[nt], a0, a1, a2, a3, b0, b1);
                    }
                }
            }
        }
        __syncthreads();
        if (nx) {
            #pragma unroll
            for (int it = 0; it < 7; it++) {
                int j = tid + it*256;
                if (j < 1664) {
                    int ci = j/104, r = j%104, y = r/26, q = r%26;
                    *(float4*)&inh[ci*424 + y*104 + q*4] = pv4[it];
                }
            }
            #pragma unroll
            for (int it = 0; it < 18; it++) {
                int tap = it >> 1;
                int r = ((it & 1) << 8) + tid;
                int ci = r >> 5, co = r & 31;
                wsh[tap*640 + ci*40 + co] = pw[it];
            }
            __syncthreads();
        }
    }
    int coA = cb + m0 + grp, coB = coA + 8;
    float bA = bias[coA], bB = bias[coB];
    int oh = oh0 + row;
    float* pA = out + ((size_t)(n*CCH + coA))*HWX + oh*WWW;
    float* pB = out + ((size_t)(n*CCH + coB))*HWX + oh*WWW;
    #pragma unroll
    for (int nt = 0; nt < 6; nt++) {
        int px = half*48 + nt*8 + 2*qid;
        pA[px]   = acc[nt][0] + bA;
        pA[px+1] = acc[nt][1] + bA;
        pB[px]   = acc[nt][2] + bB;
        pB[px+1] = acc[nt][3] + bB;
    }
}

// ---------------- ro: 1x1 128->4, fused d1-GN ----------------
__global__ void conv_ro_kernel(const float* __restrict__ y, const float* __restrict__ w,
                               const float* __restrict__ b, float* __restrict__ out,
                               const float* __restrict__ gam, const float* __restrict__ bet) {
    int t = blockIdx.x*256 + threadIdx.x;
    int n = t / HWX, p = t % HWX;
    __shared__ float ws[512];
    __shared__ float As[128], Bs[128];
    for (int j = threadIdx.x; j < 512; j += 256) ws[j] = w[j];
    if (threadIdx.x < 128) {
        int c = threadIdx.x;
        int ng = n*2 + (c >> 6);
        float mu = g_stats2[3][ng][0], rs = g_stats2[3][ng][1];
        float gm = gam[c];
        As[c] = rs*gm;
        Bs[c] = bet[c] - mu*rs*gm;
    }
    __syncthreads();
    if (t >= NNB*HWX) return;
    float a0 = b[0], a1 = b[1], a2 = b[2], a3 = b[3];
    const float* yp = y + (size_t)n*CCH*HWX + p;
    for (int ci = 0; ci < 128; ci++) {
        float v = yp[(size_t)ci*HWX];
        v = fmaf(v, As[ci], Bs[ci]);
        v = v >= 0.f ? v : SLOPE_F*v;
        a0 += v*ws[ci]; a1 += v*ws[128+ci]; a2 += v*ws[256+ci]; a3 += v*ws[384+ci];
    }
    out[((size_t)n*4 + 0)*HWX + p] = a0;
    out[((size_t)n*4 + 1)*HWX + p] = a1;
    out[((size_t)n*4 + 2)*HWX + p] = a2;
    out[((size_t)n*4 + 3)*HWX + p] = a3;
}

// ---------------- host ----------------
extern "C" void kernel_launch(void* const* d_in, const int* in_sizes, int n_in,
                              void* d_out, int out_size) {
    const float* x       = (const float*)d_in[0];
    const float* e0_w    = (const float*)d_in[1];
    const float* e0_b    = (const float*)d_in[2];
    const float* e0_g    = (const float*)d_in[3];
    const float* e0_beta = (const float*)d_in[4];
    const float* e1_w    = (const float*)d_in[5];
    const float* e1_b    = (const float*)d_in[6];
    const float* e1_g    = (const float*)d_in[7];
    const float* e1_beta = (const float*)d_in[8];
    const float* pv_w    = (const float*)d_in[9];
    const float* pv_b    = (const float*)d_in[10];
    const float* emb     = (const float*)d_in[11];
    const float* d0_w    = (const float*)d_in[12];
    const float* d0_b    = (const float*)d_in[13];
    const float* d0_g    = (const float*)d_in[14];
    const float* d0_beta = (const float*)d_in[15];
    const float* d1_w    = (const float*)d_in[16];
    const float* d1_b    = (const float*)d_in[17];
    const float* d1_g    = (const float*)d_in[18];
    const float* d1_beta = (const float*)d_in[19];
    const float* proj_w  = (const float*)d_in[20];
    const float* proj_b  = (const float*)d_in[21];
    const float* ro_w    = (const float*)d_in[22];
    const float* ro_b    = (const float*)d_in[23];
    float* out = (float*)d_out;

    float *bufA, *bufB, *zb, *hb, *yb, *wpk;
    cudaGetSymbolAddress((void**)&bufA, g_bufA);
    cudaGetSymbolAddress((void**)&bufB, g_bufB);
    cudaGetSymbolAddress((void**)&zb,   g_z);
    cudaGetSymbolAddress((void**)&hb,   g_h);
    cudaGetSymbolAddress((void**)&yb,   g_y);
    cudaGetSymbolAddress((void**)&wpk,  g_wpack);

    static cudaStream_t sA = nullptr, sB = nullptr;
    static cudaEvent_t evRoot = nullptr, evEnorm = nullptr, evPack = nullptr,
                       evStats0 = nullptr, evSkip = nullptr, evTop3 = nullptr,
                       evFin = nullptr;
    if (sA == nullptr) {
        cudaStreamCreateWithFlags(&sA, cudaStreamNonBlocking);
        cudaStreamCreateWithFlags(&sB, cudaStreamNonBlocking);
        cudaEventCreateWithFlags(&evRoot,   cudaEventDisableTiming);
        cudaEventCreateWithFlags(&evEnorm,  cudaEventDisableTiming);
        cudaEventCreateWithFlags(&evPack,   cudaEventDisableTiming);
        cudaEventCreateWithFlags(&evStats0, cudaEventDisableTiming);
        cudaEventCreateWithFlags(&evSkip,   cudaEventDisableTiming);
        cudaEventCreateWithFlags(&evTop3,   cudaEventDisableTiming);
        cudaEventCreateWithFlags(&evFin,    cudaEventDisableTiming);
        cudaFuncSetAttribute(conv_e1_mma_kernel, cudaFuncAttributeMaxDynamicSharedMemorySize,
                             E1_SMEM_FLOATS*4);
        cudaFuncSetAttribute(conv_d0_mma_kernel, cudaFuncAttributeMaxDynamicSharedMemorySize,
                             D0_SMEM_FLOATS*4);
        cudaFuncSetAttribute(conv_d1_mma_kernel, cudaFuncAttributeMaxDynamicSharedMemorySize,
                             D1_SMEM_FLOATS*4);
    }

    // fork point
    cudaEventRecord(evRoot, 0);

    // streamA: weight packing concurrent with e0
    cudaStreamWaitEvent(sA, evRoot, 0);
    init_pack_kernel<<<(9*256*128+255)/256, 256, 0, sA>>>(d1_w, d0_w, e1_w);
    cudaEventRecord(evPack, sA);

    // streamB: emb norms
    cudaStreamWaitEvent(sB, evRoot, 0);
    enorm_kernel<<<CODES/8, 256, 0, sB>>>(emb);
    cudaEventRecord(evEnorm, sB);

    // main: encoder stage 0 (raw weights, no pack dependency)
    conv_e0_kernel<<<dim3(48,4,2), 192>>>(x, e0_w, e0_b, bufA);
    // join pack before GN stats (ticket reset) and before e1 (packed weights)
    cudaStreamWaitEvent(0, evPack, 0);
    gn_part_kernel<<<dim3(8,32), 256>>>(bufA, HWX, 0);
    cudaEventRecord(evStats0, 0);

    // streamA: skip path concurrent with e1/pv/scores
    cudaStreamWaitEvent(sA, evStats0, 0);
    skip_mma_kernel<<<dim3(96,4), 256, 0, sA>>>(bufA, proj_w, proj_b, e0_g, e0_beta);
    cudaEventRecord(evSkip, sA);

    // main: prep_e1 -> e1 -> GN1 -> pv
    prep_e1_kernel<<<NNB*CCH*96/8, 256>>>(bufA, e0_g, e0_beta);
    conv_e1_mma_kernel<<<dim3(24,4,4), 256, E1_SMEM_FLOATS*4>>>(e1_b, bufB);
    gn_part_kernel<<<dim3(8,32), 256>>>(bufB, HW2, 1);
    pv_mma_kernel<<<dim3(24,2,4), 256>>>(bufB, pv_w, pv_b, e1_g, e1_beta, zb);

    // main: VQ
    cudaStreamWaitEvent(0, evEnorm, 0);
    scores_mma_kernel<<<dim3(72,8), 256>>>(emb, zb);
    top3_merge_kernel<<<ROWS/256, 256>>>();
    cudaEventRecord(evTop3, 0);

    // streamB: loss + perplexity concurrent with decoder
    cudaStreamWaitEvent(sB, evTop3, 0);
    loss_part_kernel<<<36, 256, 0, sB>>>(emb, zb);
    finalize_kernel<<<1, 1024, 0, sB>>>(out, out + (out_size - 1));
    cudaEventRecord(evFin, sB);

    // main: decoder
    prep_q_kernel<<<NNB*CCH*HH2/8, 256>>>(emb);
    conv_d0_mma_kernel<<<dim3(24,4,4), 256, D0_SMEM_FLOATS*4>>>(d0_b, hb);
    gn_part_kernel<<<dim3(8,32), 256>>>(hb, HWX, 2);
    prep_d_kernel<<<NNB*CCH*96/8, 256>>>(hb, d0_g, d0_beta);

    cudaStreamWaitEvent(0, evSkip, 0);
    conv_d1_mma_kernel<<<dim3(48,4,4), 256, D1_SMEM_FLOATS*4>>>(wpk, d1_b, yb);
    gn_part_kernel<<<dim3(8,32), 256>>>(yb, HWX, 3);

    cudaStreamWaitEvent(0, evFin, 0);
    conv_ro_kernel<<<NNB*HWX/256, 256>>>(yb, ro_w, ro_b, out + 1, d1_g, d1_beta);
}

// round 13
// speedup vs baseline: 1.0217x; 1.0217x over previous
#include <cuda_runtime.h>
#include <math.h>
#include <stdint.h>

#define NNB 4
#define CCH 128
#define HHH 96
#define WWW 96
#define HWX 9216
#define HH2 48
#define HW2 2304
#define ROWS 9216
#define CODES 1024
#define GN_EPS_F 1e-5f
#define SLOPE_F 0.2f

// ---------------- scratch ----------------
__device__ float g_bufA[NNB*CCH*HWX];
__device__ float g_bufB[NNB*CCH*HW2];
__device__ float g_z[NNB*CCH*HW2];
__device__ float g_h[NNB*CCH*HWX];
__device__ float g_y[NNB*CCH*HWX];
__device__ float g_e1h[NNB*CCH*96*104];
__device__ float g_e1l[NNB*CCH*96*104];
__device__ float g_dcomb[NNB*256*96*104];
__device__ float g_qpack[NNB*CCH*HH2*52];
__device__ float g_wpack[9*256*128];
__device__ float g_wd0[9*128*128];
__device__ float g_we1h[9*128*128];
__device__ float g_we1l[9*128*128];
__device__ float g_pv[ROWS*24];
__device__ int   g_pi[ROWS*24];
__device__ float g_en2[CODES];
__device__ float g_part[8*64*2];
__device__ float g_stats2[4][8][2];
__device__ float g_losspart[36];
__device__ int   g_idx0[ROWS];
__device__ int   g_counts[CODES];
__device__ int   g_ticket[8];

__device__ __forceinline__ float to_tf32(float v) {
    uint32_t u;
    asm("cvt.rna.tf32.f32 %0, %1;" : "=r"(u) : "f"(v));
    return __uint_as_float(u);
}

__device__ __forceinline__ void mma_tf32(float c[4], float a0, float a1, float a2, float a3,
                                         float b0, float b1) {
    uint32_t A0 = __float_as_uint(a0), A1 = __float_as_uint(a1);
    uint32_t A2 = __float_as_uint(a2), A3 = __float_as_uint(a3);
    uint32_t B0 = __float_as_uint(b0), B1 = __float_as_uint(b1);
    asm volatile(
        "mma.sync.aligned.m16n8k8.row.col.f32.tf32.tf32.f32 "
        "{%0,%1,%2,%3},{%4,%5,%6,%7},{%8,%9},{%0,%1,%2,%3};\n"
        : "+f"(c[0]), "+f"(c[1]), "+f"(c[2]), "+f"(c[3])
        : "r"(A0), "r"(A1), "r"(A2), "r"(A3), "r"(B0), "r"(B1));
}

// ---------------- combined init + weight packing (e1/d0/d1 only) ----------------
__global__ void init_pack_kernel(const float* __restrict__ d1w, const float* __restrict__ d0w,
                                 const float* __restrict__ e1w) {
    int t = blockIdx.x*256 + threadIdx.x;
    if (t < CODES) g_counts[t] = 0;
    if (t < 8) g_ticket[t] = 0;
    if (t < 9*256*128) {
        int co = t & 127, ci = (t >> 7) & 255, tap = t >> 15;
        g_wpack[((size_t)tap*256 + ci)*128 + co] = to_tf32(d1w[((size_t)co*256 + ci)*9 + tap]);
    }
    if (t < 9*128*128) {
        int co = t & 127, ci = (t >> 7) & 127, tap = t >> 14;
        g_wd0[((size_t)tap*128 + ci)*128 + co] = to_tf32(d0w[((size_t)ci*128 + co)*9 + tap]);
        float v = e1w[((size_t)co*128 + ci)*9 + tap];
        float h = to_tf32(v);
        g_we1h[((size_t)tap*128 + ci)*128 + co] = h;
        g_we1l[((size_t)tap*128 + ci)*128 + co] = to_tf32(v - h);
    }
}

// ---------------- e0: conv3x3 s1 p1, 4->128, co-split, raw weights ----------------
__global__ void __launch_bounds__(192) conv_e0_kernel(const float* __restrict__ x,
                                                      const float* __restrict__ w,
                                                      const float* __restrict__ b,
                                                      float* __restrict__ out) {
    int oh0 = blockIdx.x*2, n = blockIdx.y, ch = blockIdx.z*64;
    __shared__ float xs[4][4][98];
    __shared__ float ws[36*64];
    int tid = threadIdx.x;
    for (int j = tid; j < 4*4*98; j += 192) {
        int ci = j/392, r2 = j%392, y = r2/98, xx = r2%98;
        int ih = oh0 - 1 + y, iw = xx - 1;
        float v = 0.f;
        if (ih >= 0 && ih < HHH && iw >= 0 && iw < WWW)
            v = x[((size_t)(n*4 + ci))*HWX + ih*WWW + iw];
        xs[ci][y][xx] = v;
    }
    for (int j = tid; j < 36*64; j += 192) {
        int tap = j >> 6, co = j & 63;
        ws[j] = w[(ch + co)*36 + tap];
    }
    __syncthreads();
    int r = tid/96, ow = tid%96, oh = oh0 + r;
    float iv[36];
    #pragma unroll
    for (int ci = 0; ci < 4; ci++)
        #pragma unroll
        for (int kh = 0; kh < 3; kh++)
            #pragma unroll
            for (int kw = 0; kw < 3; kw++)
                iv[ci*9 + kh*3 + kw] = xs[ci][r + kh][ow + kw];
    for (int co0 = 0; co0 < 64; co0 += 4) {
        float4 acc = *(const float4*)&b[ch + co0];
        #pragma unroll
        for (int tap = 0; tap < 36; tap++) {
            float4 wv = *(const float4*)&ws[tap*64 + co0];
            acc.x += iv[tap]*wv.x; acc.y += iv[tap]*wv.y;
            acc.z += iv[tap]*wv.z; acc.w += iv[tap]*wv.w;
        }
        float* op = out + ((size_t)(n*CCH + ch + co0))*HWX + oh*WWW + ow;
        op[0] = acc.x; op[HWX] = acc.y; op[2*HWX] = acc.z; op[3*HWX] = acc.w;
    }
}

// ---------------- GroupNorm stats: float4 loads, 64 partial blocks, fused finalize ----------------
__global__ void gn_part_kernel(const float* __restrict__ buf, int hw, int stage) {
    int ng = blockIdx.x, bb = blockIdx.y;   // y in 0..63
    int n = ng >> 1, g = ng & 1;
    const float4* p4 = (const float4*)(buf + ((size_t)n*CCH + g*64)*hw);
    int len4 = 16*hw;
    float s = 0.f, ss = 0.f;
    for (int i = bb*256 + threadIdx.x; i < len4; i += 64*256) {
        float4 v = p4[i];
        s += (v.x + v.y) + (v.z + v.w);
        ss += v.x*v.x + v.y*v.y + v.z*v.z + v.w*v.w;
    }
    __shared__ float sh[256], sh2[256];
    __shared__ int flag;
    sh[threadIdx.x] = s; sh2[threadIdx.x] = ss; __syncthreads();
    for (int o = 128; o; o >>= 1) {
        if (threadIdx.x < o) { sh[threadIdx.x] += sh[threadIdx.x+o]; sh2[threadIdx.x] += sh2[threadIdx.x+o]; }
        __syncthreads();
    }
    if (threadIdx.x == 0) {
        g_part[(ng*64+bb)*2] = sh[0]; g_part[(ng*64+bb)*2+1] = sh2[0];
        __threadfence();
        int done = atomicAdd(&g_ticket[stage], 1);
        flag = (done == 511);
    }
    __syncthreads();
    if (flag && threadIdx.x < 8) {
        int g2 = threadIdx.x;
        float s2 = 0.f, ss2 = 0.f;
        for (int b2 = 0; b2 < 64; b2++) { s2 += g_part[(g2*64+b2)*2]; ss2 += g_part[(g2*64+b2)*2+1]; }
        float cnt = 64.f * (float)hw;
        float mu  = s2 / cnt;
        float var = ss2 / cnt - mu*mu;
        g_stats2[stage][g2][0] = mu; g_stats2[stage][g2][1] = rsqrtf(var + GN_EPS_F);
    }
}

// ---------------- prep_e1 ----------------
__global__ void __launch_bounds__(256) prep_e1_kernel(const float* __restrict__ in,
                                                      const float* __restrict__ gam,
                                                      const float* __restrict__ bet) {
    int gw = blockIdx.x*8 + (threadIdx.x >> 5);
    int lane = threadIdx.x & 31;
    int ih = gw % 96; int t = gw / 96; int ci = t & 127; int n = t >> 7;
    int ng = n*2 + (ci >> 6);
    float rs = g_stats2[0][ng][1], mu = g_stats2[0][ng][0];
    float A = rs*gam[ci];
    float B = bet[ci] - mu*A;
    const float* src = in + ((size_t)(n*CCH + ci))*HWX + ih*WWW;
    float* dh = g_e1h + (size_t)gw*104;
    float* dl = g_e1l + (size_t)gw*104;
    #pragma unroll
    for (int r = 0; r < 3; r++) {
        int iw = lane + r*32;
        float v = src[iw];
        v = fmaf(v, A, B);
        v = v >= 0.f ? v : SLOPE_F*v;
        float h = to_tf32(v);
        int dst = (iw & 1) ? ((iw+1) >> 1) : (52 + (iw >> 1));
        dh[dst] = h; dl[dst] = to_tf32(v - h);
    }
    if (lane == 0) { dh[0] = 0.f; dl[0] = 0.f; }
}

// ---------------- prep_d ----------------
__global__ void __launch_bounds__(256) prep_d_kernel(const float* __restrict__ in,
                                                     const float* __restrict__ gam,
                                                     const float* __restrict__ bet) {
    int gw = blockIdx.x*8 + (threadIdx.x >> 5);
    int lane = threadIdx.x & 31;
    int ih = gw % 96; int t = gw / 96; int ci = t & 127; int n = t >> 7;
    int ng = n*2 + (ci >> 6);
    float rs = g_stats2[2][ng][1], mu = g_stats2[2][ng][0];
    float A = rs*gam[ci];
    float B = bet[ci] - mu*A;
    const float* src = in + ((size_t)(n*CCH + ci))*HWX + ih*WWW;
    float* dst = g_dcomb + ((size_t)((n*256 + ci)*96 + ih))*104;
    #pragma unroll
    for (int r = 0; r < 3; r++) {
        int iw = lane + r*32;
        float v = src[iw];
        v = fmaf(v, A, B);
        v = v >= 0.f ? v : SLOPE_F*v;
        dst[iw + 1] = to_tf32(v);
    }
    if (lane == 0) dst[0] = 0.f;
    if (lane < 7) dst[97 + lane] = 0.f;
}

// ---------------- prep_q ----------------
__global__ void __launch_bounds__(256) prep_q_kernel(const float* __restrict__ emb) {
    int gw = blockIdx.x*8 + (threadIdx.x >> 5);
    int lane = threadIdx.x & 31;
    int ih = gw % HH2; int t = gw / HH2; int ci = t & 127; int n = t >> 7;
    const int* idx = g_idx0 + n*HW2 + ih*HH2;
    float* dst = g_qpack + (size_t)gw*52;
    dst[lane] = to_tf32(emb[(size_t)idx[lane]*CCH + ci]);
    if (lane < 16) dst[32 + lane] = to_tf32(emb[(size_t)idx[32 + lane]*CCH + ci]);
    if (lane < 4) dst[48 + lane] = 0.f;
}

// ---------------- e1: split-tf32 MMA, pipelined ----------------
#define E1_SMEM_FLOATS (4160+4160+2880+2880)
__global__ void __launch_bounds__(256) conv_e1_mma_kernel(
        const float* __restrict__ bias, float* __restrict__ out) {
    extern __shared__ float smem[];
    float* inh = smem;
    float* inl = smem + 4160;
    float* wsh = smem + 8320;
    float* wsl = smem + 11200;
    int oh0 = blockIdx.x*2, cb = blockIdx.y*32, n = blockIdx.z;
    int tid = threadIdx.x, lane = tid & 31, wid = tid >> 5;
    int row = (wid >> 2) & 1, m0 = ((wid >> 1) & 1)*16, half = wid & 1;
    int grp = lane >> 2, qid = lane & 3;
    float acc[3][4];
    #pragma unroll
    for (int i = 0; i < 3; i++)
        #pragma unroll
        for (int j = 0; j < 4; j++) acc[i][j] = 0.f;

    const float4 zero4 = make_float4(0.f, 0.f, 0.f, 0.f);
    for (int j = tid; j < 8*5*26; j += 256) {
        int ci = j/130, r = j%130, y = r/26, q = r%26;
        int ih = 2*oh0 - 1 + y;
        float4 vh = zero4, vl = zero4;
        if (ih >= 0 && ih < 96) {
            size_t srow = ((size_t)((n*CCH + ci)*96 + ih))*26 + q;
            vh = ((const float4*)g_e1h)[srow];
            vl = ((const float4*)g_e1l)[srow];
        }
        *(float4*)&inh[ci*520 + y*104 + q*4] = vh;
        *(float4*)&inl[ci*520 + y*104 + q*4] = vl;
    }
    {
        int ciw = tid >> 5, cow = tid & 31;
        #pragma unroll
        for (int it = 0; it < 9; it++) {
            size_t src = ((size_t)(it*128 + ciw))*128 + cb + cow;
            int dst = it*320 + ciw*40 + cow;
            wsh[dst] = g_we1h[src];
            wsl[dst] = g_we1l[src];
        }
    }
    __syncthreads();

    for (int c0 = 0; c0 < 128; c0 += 8) {
        float4 ph[5], pl[5];
        float pwh[9], pwl[9];
        bool nx = (c0 < 120);
        if (nx) {
            int cn = c0 + 8;
            #pragma unroll
            for (int it = 0; it < 5; it++) {
                int j = tid + it*256;
                ph[it] = zero4; pl[it] = zero4;
                if (j < 1040) {
                    int ci = j/130, r = j%130, y = r/26, q = r%26;
                    int ih = 2*oh0 - 1 + y;
                    if (ih >= 0 && ih < 96) {
                        size_t srow = ((size_t)((n*CCH + cn+ci)*96 + ih))*26 + q;
                        ph[it] = ((const float4*)g_e1h)[srow];
                        pl[it] = ((const float4*)g_e1l)[srow];
                    }
                }
            }
            int ciw = tid >> 5, cow = tid & 31;
            #pragma unroll
            for (int it = 0; it < 9; it++) {
                size_t src = ((size_t)(it*128 + cn+ciw))*128 + cb + cow;
                pwh[it] = g_we1h[src];
                pwl[it] = g_we1l[src];
            }
        }
        #pragma unroll
        for (int kh = 0; kh < 3; kh++) {
            #pragma unroll
            for (int kw = 0; kw < 3; kw++) {
                int tap = kh*3 + kw;
                int wb = tap*320 + qid*40 + m0 + grp;
                float ah0 = wsh[wb],     ah1 = wsh[wb+8];
                float ah2 = wsh[wb+160], ah3 = wsh[wb+168];
                float al0 = wsl[wb],     al1 = wsl[wb+8];
                float al2 = wsl[wb+160], al3 = wsl[wb+168];
                int bb = qid*520 + (2*row + kh)*104 + (kw & 1)*52 + (kw >> 1) + half*24 + grp;
                #pragma unroll
                for (int nt = 0; nt < 3; nt++) {
                    float bh0 = inh[bb + nt*8], bh1 = inh[bb + 2080 + nt*8];
                    float bl0 = inl[bb + nt*8], bl1 = inl[bb + 2080 + nt*8];
                    mma_tf32(acc[nt], ah0, ah1, ah2, ah3, bh0, bh1);
                    mma_tf32(acc[nt], ah0, ah1, ah2, ah3, bl0, bl1);
                    mma_tf32(acc[nt], al0, al1, al2, al3, bh0, bh1);
                }
            }
        }
        __syncthreads();
        if (nx) {
            #pragma unroll
            for (int it = 0; it < 5; it++) {
                int j = tid + it*256;
                if (j < 1040) {
                    int ci = j/130, r = j%130, y = r/26, q = r%26;
                    *(float4*)&inh[ci*520 + y*104 + q*4] = ph[it];
                    *(float4*)&inl[ci*520 + y*104 + q*4] = pl[it];
                }
            }
            int ciw = tid >> 5, cow = tid & 31;
            #pragma unroll
            for (int it = 0; it < 9; it++) {
                int dst = it*320 + ciw*40 + cow;
                wsh[dst] = pwh[it];
                wsl[dst] = pwl[it];
            }
            __syncthreads();
        }
    }
    int coA = cb + m0 + grp, coB = coA + 8;
    float bA = bias[coA], bB = bias[coB];
    int oh = oh0 + row;
    float* pA = out + ((size_t)(n*CCH + coA))*HW2 + oh*HH2;
    float* pB = out + ((size_t)(n*CCH + coB))*HW2 + oh*HH2;
    #pragma unroll
    for (int nt = 0; nt < 3; nt++) {
        int px = half*24 + nt*8 + 2*qid;
        pA[px]   = acc[nt][0] + bA;
        pA[px+1] = acc[nt][1] + bA;
        pB[px]   = acc[nt][2] + bB;
        pB[px+1] = acc[nt][3] + bB;
    }
}

// ---------------- pv: 1x1 split-tf32 MMA, pipelined ----------------
__global__ void __launch_bounds__(256) pv_mma_kernel(
        const float* __restrict__ in, const float* __restrict__ w,
        const float* __restrict__ bias, const float* __restrict__ gam,
        const float* __restrict__ bet, float* __restrict__ out) {
    __shared__ float inh[16*104], inl[16*104], wh[16*72], wl[16*72];
    __shared__ float As[128], Bs[128];
    int pt = blockIdx.x*96, cb = blockIdx.y*64, n = blockIdx.z;
    int tid = threadIdx.x, lane = tid & 31, wid = tid >> 5;
    int half = wid >> 2, m0 = (wid & 3)*16;
    int grp = lane >> 2, qid = lane & 3;
    if (tid < 128) {
        int ng = n*2 + (tid >> 6);
        float mu = g_stats2[1][ng][0], rs = g_stats2[1][ng][1];
        float gm = gam[tid];
        As[tid] = rs*gm;
        Bs[tid] = bet[tid] - mu*rs*gm;
    }
    __syncthreads();
    float acc[6][4];
    #pragma unroll
    for (int i = 0; i < 6; i++)
        #pragma unroll
        for (int j = 0; j < 4; j++) acc[i][j] = 0.f;

    #pragma unroll
    for (int it = 0; it < 6; it++) {
        int j = tid + it*256;
        int k = j/96, px = j%96;
        float v = in[((size_t)(n*CCH + k))*HW2 + pt + px];
        v = fmaf(v, As[k], Bs[k]);
        v = v >= 0.f ? v : SLOPE_F*v;
        float h = to_tf32(v);
        inh[k*104 + px] = h; inl[k*104 + px] = to_tf32(v - h);
    }
    #pragma unroll
    for (int it = 0; it < 4; it++) {
        int j = tid + it*256;
        int k = j >> 6, co = j & 63;
        float v = w[(size_t)(cb+co)*128 + k];
        float h = to_tf32(v);
        wh[k*72 + co] = h; wl[k*72 + co] = to_tf32(v - h);
    }
    __syncthreads();

    for (int c0 = 0; c0 < 128; c0 += 16) {
        float pin[6], pwv[4];
        bool nx = (c0 < 112);
        if (nx) {
            int cn = c0 + 16;
            #pragma unroll
            for (int it = 0; it < 6; it++) {
                int j = tid + it*256;
                int k = j/96, px = j%96;
                pin[it] = in[((size_t)(n*CCH + cn+k))*HW2 + pt + px];
            }
            #pragma unroll
            for (int it = 0; it < 4; it++) {
                int j = tid + it*256;
                int k = j >> 6, co = j & 63;
                pwv[it] = w[(size_t)(cb+co)*128 + cn + k];
            }
        }
        #pragma unroll
        for (int ks = 0; ks < 2; ks++) {
            int wb = (ks*8 + qid)*72 + m0 + grp;
            float ah0 = wh[wb], ah1 = wh[wb+8], ah2 = wh[wb+288], ah3 = wh[wb+296];
            float al0 = wl[wb], al1 = wl[wb+8], al2 = wl[wb+288], al3 = wl[wb+296];
            int bb = (ks*8 + qid)*104 + half*48 + grp;
            #pragma unroll
            for (int nt = 0; nt < 6; nt++) {
                float bh0 = inh[bb + nt*8], bh1 = inh[bb + 416 + nt*8];
                float bl0 = inl[bb + nt*8], bl1 = inl[bb + 416 + nt*8];
                mma_tf32(acc[nt], ah0, ah1, ah2, ah3, bh0, bh1);
                mma_tf32(acc[nt], ah0, ah1, ah2, ah3, bl0, bl1);
                mma_tf32(acc[nt], al0, al1, al2, al3, bh0, bh1);
            }
        }
        __syncthreads();
        if (nx) {
            int cn = c0 + 16;
            #pragma unroll
            for (int it = 0; it < 6; it++) {
                int j = tid + it*256;
                int k = j/96, px = j%96;
                float v = fmaf(pin[it], As[cn+k], Bs[cn+k]);
                v = v >= 0.f ? v : SLOPE_F*v;
                float h = to_tf32(v);
                inh[k*104 + px] = h; inl[k*104 + px] = to_tf32(v - h);
            }
            #pragma unroll
            for (int it = 0; it < 4; it++) {
                int j = tid + it*256;
                int k = j >> 6, co = j & 63;
                float h = to_tf32(pwv[it]);
                wh[k*72 + co] = h; wl[k*72 + co] = to_tf32(pwv[it] - h);
            }
            __syncthreads();
        }
    }
    int coA = cb + m0 + grp, coB = coA + 8;
    float bA = bias[coA], bB = bias[coB];
    float* pA = out + ((size_t)(n*CCH + coA))*HW2 + pt;
    float* pB = out + ((size_t)(n*CCH + coB))*HW2 + pt;
    #pragma unroll
    for (int nt = 0; nt < 6; nt++) {
        int px = half*48 + nt*8 + 2*qid;
        pA[px]   = acc[nt][0] + bA;
        pA[px+1] = acc[nt][1] + bA;
        pB[px]   = acc[nt][2] + bB;
        pB[px+1] = acc[nt][3] + bB;
    }
}

// ---------------- skip: 1x1 tf32 MMA, pipelined, writes tf32 into g_dcomb ----------------
__global__ void __launch_bounds__(256) skip_mma_kernel(
        const float* __restrict__ in, const float* __restrict__ w,
        const float* __restrict__ bias, const float* __restrict__ gam,
        const float* __restrict__ bet) {
    __shared__ float inh[16*104], wh[16*136];
    __shared__ float As[128], Bs[128];
    int oh = blockIdx.x, n = blockIdx.y;
    int pt = oh*96;
    int tid = threadIdx.x, lane = tid & 31, wid = tid >> 5;
    int m0 = wid*16;
    int grp = lane >> 2, qid = lane & 3;
    if (tid < 128) {
        int ng = n*2 + (tid >> 6);
        float mu = g_stats2[0][ng][0], rs = g_stats2[0][ng][1];
        float gm = gam[tid];
        As[tid] = rs*gm;
        Bs[tid] = bet[tid] - mu*rs*gm;
    }
    for (int j = tid; j < 128*8; j += 256) {
        int co = j >> 3, c = j & 7;
        int col = (c == 0) ? 0 : 96 + c;
        g_dcomb[((size_t)((n*256 + 128 + co)*96 + oh))*104 + col] = 0.f;
    }
    __syncthreads();
    float acc[12][4];
    #pragma unroll
    for (int i = 0; i < 12; i++)
        #pragma unroll
        for (int j = 0; j < 4; j++) acc[i][j] = 0.f;

    #pragma unroll
    for (int it = 0; it < 6; it++) {
        int j = tid + it*256;
        int k = j/96, px = j%96;
        float v = in[((size_t)(n*CCH + k))*HWX + pt + px];
        v = fmaf(v, As[k], Bs[k]);
        v = v >= 0.f ? v : SLOPE_F*v;
        inh[k*104 + px] = to_tf32(v);
    }
    #pragma unroll
    for (int it = 0; it < 8; it++) {
        int j = tid + it*256;
        int k = j & 15, co = j >> 4;
        wh[k*136 + co] = to_tf32(w[(size_t)co*128 + k]);
    }
    __syncthreads();

    for (int c0 = 0; c0 < 128; c0 += 16) {
        float pin[6], pwv[8];
        bool nx = (c0 < 112);
        if (nx) {
            int cn = c0 + 16;
            #pragma unroll
            for (int it = 0; it < 6; it++) {
                int j = tid + it*256;
                int k = j/96, px = j%96;
                pin[it] = in[((size_t)(n*CCH + cn+k))*HWX + pt + px];
            }
            #pragma unroll
            for (int it = 0; it < 8; it++) {
                int j = tid + it*256;
                int k = j & 15, co = j >> 4;
                pwv[it] = w[(size_t)co*128 + cn + k];
            }
        }
        #pragma unroll
        for (int ks = 0; ks < 2; ks++) {
            int wb = (ks*8 + qid)*136 + m0 + grp;
            float a0 = wh[wb], a1 = wh[wb+8], a2 = wh[wb+544], a3 = wh[wb+552];
            int bb = (ks*8 + qid)*104 + grp;
            #pragma unroll
            for (int nt = 0; nt < 12; nt++) {
                float b0 = inh[bb + nt*8], b1 = inh[bb + 416 + nt*8];
                mma_tf32(acc[nt], a0, a1, a2, a3, b0, b1);
            }
        }
        __syncthreads();
        if (nx) {
            int cn = c0 + 16;
            #pragma unroll
            for (int it = 0; it < 6; it++) {
                int j = tid + it*256;
                int k = j/96, px = j%96;
                float v = fmaf(pin[it], As[cn+k], Bs[cn+k]);
                v = v >= 0.f ? v : SLOPE_F*v;
                inh[k*104 + px] = to_tf32(v);
            }
            #pragma unroll
            for (int it = 0; it < 8; it++) {
                int j = tid + it*256;
                int k = j & 15, co = j >> 4;
                wh[k*136 + co] = to_tf32(pwv[it]);
            }
            __syncthreads();
        }
    }
    int coA = m0 + grp, coB = coA + 8;
    float bA = bias[coA], bB = bias[coB];
    float* pA = g_dcomb + ((size_t)((n*256 + 128 + coA)*96 + oh))*104 + 1;
    float* pB = g_dcomb + ((size_t)((n*256 + 128 + coB)*96 + oh))*104 + 1;
    #pragma unroll
    for (int nt = 0; nt < 12; nt++) {
        int px = nt*8 + 2*qid;
        pA[px]   = to_tf32(acc[nt][0] + bA);
        pA[px+1] = to_tf32(acc[nt][1] + bA);
        pB[px]   = to_tf32(acc[nt][2] + bB);
        pB[px+1] = to_tf32(acc[nt][3] + bB);
    }
}

// ---------------- emb norms ----------------
__global__ void enorm_kernel(const float* __restrict__ emb) {
    int wp = (blockIdx.x*256 + threadIdx.x) >> 5;
    int lane = threadIdx.x & 31;
    if (wp >= CODES) return;
    const float* e = emb + (size_t)wp*CCH;
    float s = 0.f;
    for (int d = lane; d < CCH; d += 32) { float v = e[d]; s += v*v; }
    for (int o = 16; o; o >>= 1) s += __shfl_down_sync(0xffffffffu, s, o);
    if (lane == 0) g_en2[wp] = s;
}

// ---------------- top3 insert ----------------
__device__ __forceinline__ void topk_insert(float v, int i,
        float& v0, int& i0, float& v1, int& i1, float& v2, int& i2) {
    bool b2 = (v < v2) || (v == v2 && i < i2);
    if (!b2) return;
    bool b1 = (v < v1) || (v == v1 && i < i1);
    bool b0 = (v < v0) || (v == v0 && i < i0);
    if (b0)      { v2=v1;i2=i1; v1=v0;i1=i0; v0=v;i0=i; }
    else if (b1) { v2=v1;i2=i1; v1=v; i1=i; }
    else         { v2=v; i2=i; }
}

// ---------------- scores: split-tf32 MMA + fused partial top3, pipelined ----------------
__global__ void __launch_bounds__(256) scores_mma_kernel(const float* __restrict__ emb,
                                                         const float* __restrict__ z) {
    __shared__ float zh[16*136], zl[16*136], eh[16*136], el[16*136];
    int r0 = blockIdx.x*128, c0 = blockIdx.y*128;
    int n0 = r0 / HW2, p0 = r0 % HW2;
    int tid = threadIdx.x, lane = tid & 31, wid = tid >> 5;
    int m0 = wid*16;
    int grp = lane >> 2, qid = lane & 3;
    float acc[16][4];
    #pragma unroll
    for (int i = 0; i < 16; i++)
        #pragma unroll
        for (int j = 0; j < 4; j++) acc[i][j] = 0.f;

    #pragma unroll
    for (int it = 0; it < 8; it++) {
        int j = tid + it*256;
        int k = j >> 7, row = j & 127;
        float v = z[((size_t)(n0*CCH + k))*HW2 + p0 + row];
        float h = to_tf32(v);
        zh[k*136 + row] = h; zl[k*136 + row] = to_tf32(v - h);
    }
    #pragma unroll
    for (int it = 0; it < 8; it++) {
        int j = tid + it*256;
        int cd = j >> 4, k = j & 15;
        float v = emb[(size_t)(c0+cd)*CCH + k];
        float h = to_tf32(v);
        eh[k*136 + cd] = h; el[k*136 + cd] = to_tf32(v - h);
    }
    __syncthreads();

    for (int k0 = 0; k0 < 128; k0 += 16) {
        float pz[8], pe[8];
        bool nx = (k0 < 112);
        if (nx) {
            int kn = k0 + 16;
            #pragma unroll
            for (int it = 0; it < 8; it++) {
                int j = tid + it*256;
                int k = j >> 7, row = j & 127;
                pz[it] = z[((size_t)(n0*CCH + kn + k))*HW2 + p0 + row];
            }
            #pragma unroll
            for (int it = 0; it < 8; it++) {
                int j = tid + it*256;
                int cd = j >> 4, k = j & 15;
                pe[it] = emb[(size_t)(c0+cd)*CCH + kn + k];
            }
        }
        #pragma unroll
        for (int ks = 0; ks < 2; ks++) {
            int wb = (ks*8 + qid)*136 + m0 + grp;
            float ah0 = zh[wb], ah1 = zh[wb+8], ah2 = zh[wb+544], ah3 = zh[wb+552];
            float al0 = zl[wb], al1 = zl[wb+8], al2 = zl[wb+544], al3 = zl[wb+552];
            int bb = (ks*8 + qid)*136 + grp;
            #pragma unroll
            for (int nt = 0; nt < 16; nt++) {
                float bh0 = eh[bb + nt*8], bh1 = eh[bb + 544 + nt*8];
                float bl0 = el[bb + nt*8], bl1 = el[bb + 544 + nt*8];
                mma_tf32(acc[nt], ah0, ah1, ah2, ah3, bh0, bh1);
                mma_tf32(acc[nt], ah0, ah1, ah2, ah3, bl0, bl1);
                mma_tf32(acc[nt], al0, al1, al2, al3, bh0, bh1);
            }
        }
        __syncthreads();
        if (nx) {
            #pragma unroll
            for (int it = 0; it < 8; it++) {
                int j = tid + it*256;
                int k = j >> 7, row = j & 127;
                float h = to_tf32(pz[it]);
                zh[k*136 + row] = h; zl[k*136 + row] = to_tf32(pz[it] - h);
            }
            #pragma unroll
            for (int it = 0; it < 8; it++) {
                int j = tid + it*256;
                int cd = j >> 4, k = j & 15;
                float h = to_tf32(pe[it]);
                eh[k*136 + cd] = h; el[k*136 + cd] = to_tf32(pe[it] - h);
            }
            __syncthreads();
        }
    }
    const float FMAXV = 3.402823466e38f;
    float av0 = FMAXV, av1 = FMAXV, av2 = FMAXV;
    float bv0 = FMAXV, bv1 = FMAXV, bv2 = FMAXV;
    int ai0 = 0x7fffffff, ai1 = 0x7fffffff, ai2 = 0x7fffffff;
    int bi0 = 0x7fffffff, bi1 = 0x7fffffff, bi2 = 0x7fffffff;
    #pragma unroll
    for (int nt = 0; nt < 16; nt++) {
        int code = c0 + nt*8 + 2*qid;
        float e2a = g_en2[code], e2b = g_en2[code+1];
        topk_insert(e2a - 2.f*acc[nt][0], code,   av0,ai0,av1,ai1,av2,ai2);
        topk_insert(e2b - 2.f*acc[nt][1], code+1, av0,ai0,av1,ai1,av2,ai2);
        topk_insert(e2a - 2.f*acc[nt][2], code,   bv0,bi0,bv1,bi1,bv2,bi2);
        topk_insert(e2b - 2.f*acc[nt][3], code+1, bv0,bi0,bv1,bi1,bv2,bi2);
    }
    #pragma unroll
    for (int off = 1; off <= 2; off <<= 1) {
        float t0 = __shfl_xor_sync(0xffffffffu, av0, off); int t0i = __shfl_xor_sync(0xffffffffu, ai0, off);
        float t1 = __shfl_xor_sync(0xffffffffu, av1, off); int t1i = __shfl_xor_sync(0xffffffffu, ai1, off);
        float t2 = __shfl_xor_sync(0xffffffffu, av2, off); int t2i = __shfl_xor_sync(0xffffffffu, ai2, off);
        topk_insert(t0, t0i, av0,ai0,av1,ai1,av2,ai2);
        topk_insert(t1, t1i, av0,ai0,av1,ai1,av2,ai2);
        topk_insert(t2, t2i, av0,ai0,av1,ai1,av2,ai2);
        float u0 = __shfl_xor_sync(0xffffffffu, bv0, off); int u0i = __shfl_xor_sync(0xffffffffu, bi0, off);
        float u1 = __shfl_xor_sync(0xffffffffu, bv1, off); int u1i = __shfl_xor_sync(0xffffffffu, bi1, off);
        float u2 = __shfl_xor_sync(0xffffffffu, bv2, off); int u2i = __shfl_xor_sync(0xffffffffu, bi2, off);
        topk_insert(u0, u0i, bv0,bi0,bv1,bi1,bv2,bi2);
        topk_insert(u1, u1i, bv0,bi0,bv1,bi1,bv2,bi2);
        topk_insert(u2, u2i, bv0,bi0,bv1,bi1,bv2,bi2);
    }
    if (qid == 0) {
        int rowA = r0 + m0 + grp;
        int baseA = rowA*24 + blockIdx.y*3;
        g_pv[baseA] = av0; g_pi[baseA] = ai0;
        g_pv[baseA+1] = av1; g_pi[baseA+1] = ai1;
        g_pv[baseA+2] = av2; g_pi[baseA+2] = ai2;
        int baseB = (rowA+8)*24 + blockIdx.y*3;
        g_pv[baseB] = bv0; g_pi[baseB] = bi0;
        g_pv[baseB+1] = bv1; g_pi[baseB+1] = bi1;
        g_pv[baseB+2] = bv2; g_pi[baseB+2] = bi2;
    }
}

// ---------------- top3 merge + counts ----------------
__global__ void top3_merge_kernel() {
    int t = blockIdx.x*256 + threadIdx.x;
    if (t >= ROWS) return;
    float v0 = 3.402823466e38f, v1 = v0, v2 = v0;
    int i0 = 0x7fffffff, i1 = 0x7fffffff, i2 = 0x7fffffff;
    #pragma unroll
    for (int j = 0; j < 24; j++)
        topk_insert(g_pv[t*24+j], g_pi[t*24+j], v0,i0,v1,i1,v2,i2);
    g_idx0[t] = i0;
    atomicAdd(&g_counts[i2], 1);
}

// ---------------- loss ----------------
__global__ void loss_part_kernel(const float* __restrict__ emb, const float* __restrict__ z) {
    int row = blockIdx.x*256 + threadIdx.x;
    int n = row / HW2, p = row % HW2;
    const float* e = emb + (size_t)g_idx0[row]*CCH;
    float s = 0.f;
    for (int d = 0; d < CCH; d++) {
        float zv = z[((size_t)(n*CCH + d))*HW2 + p];
        float df = e[d] - zv; s += df*df;
    }
    __shared__ float sh[256];
    sh[threadIdx.x] = s; __syncthreads();
    for (int o = 128; o; o >>= 1) { if (threadIdx.x < o) sh[threadIdx.x] += sh[threadIdx.x+o]; __syncthreads(); }
    if (threadIdx.x == 0) g_losspart[blockIdx.x] = sh[0];
}

// ---------------- finalize ----------------
__global__ void finalize_kernel(float* out0, float* outp) {
    __shared__ float sh[1024];
    int t = threadIdx.x;
    float p = (float)g_counts[t] / (float)ROWS;
    sh[t] = p * logf(p + 1e-10f);
    __syncthreads();
    for (int o = 512; o; o >>= 1) { if (t < o) sh[t] += sh[t+o]; __syncthreads(); }
    if (t == 0) {
        outp[0] = expf(-sh[0]);
        float s = 0.f;
        for (int bb = 0; bb < 36; bb++) s += g_losspart[bb];
        out0[0] = 0.25f * s / ((float)ROWS * (float)CCH);
    }
}

// ---------------- d0: transpose conv parity streams, pipelined ----------------
#define D0_SMEM_FLOATS (16*168 + 9*16*40)
#define D0_STREAM(tap, cls, ro, sh)                                          \
    {                                                                        \
        int wb = (tap)*640 + (ks*8 + qid)*40 + m0 + grp;                     \
        float a0 = ws[wb],     a1 = ws[wb+8];                                \
        float a2 = ws[wb+160], a3 = ws[wb+168];                              \
        int bb = (ks*8 + qid)*168 + (sub + (ro))*56 + (sh) + half*24 + grp;  \
        _Pragma("unroll")                                                    \
        for (int nt = 0; nt < 3; nt++) {                                     \
            float b0 = inp[bb + nt*8];                                       \
            float b1 = inp[bb + 672 + nt*8];                                 \
            mma_tf32(acc[cls][nt], a0, a1, a2, a3, b0, b1);                  \
        }                                                                    \
    }
__global__ void __launch_bounds__(256) conv_d0_mma_kernel(
        const float* __restrict__ bias, float* __restrict__ out) {
    extern __shared__ float smem[];
    float* inp = smem;
    float* ws  = smem + 16*168;
    int i0 = blockIdx.x*2, cb = blockIdx.y*32, n = blockIdx.z;
    int tid = threadIdx.x, lane = tid & 31, wid = tid >> 5;
    int sub = (wid >> 2) & 1, m0 = ((wid >> 1) & 1)*16, half = wid & 1;
    int grp = lane >> 2, qid = lane & 3;
    float acc[4][3][4];
    #pragma unroll
    for (int c = 0; c < 4; c++)
        #pragma unroll
        for (int i = 0; i < 3; i++)
            #pragma unroll
            for (int j = 0; j < 4; j++) acc[c][i][j] = 0.f;

    const float4 zero4 = make_float4(0.f, 0.f, 0.f, 0.f);
    for (int j = tid; j < 16*3*13; j += 256) {
        int ci = j/39, r = j%39, y = r/13, q = r%13;
        int ih = i0 + y;
        float4 v = zero4;
        if (ih < HH2)
            v = ((const float4*)g_qpack)[((size_t)((n*CCH + ci)*HH2 + ih))*13 + q];
        *(float4*)&inp[ci*168 + y*56 + q*4] = v;
    }
    #pragma unroll
    for (int it = 0; it < 18; it++) {
        int tap = it >> 1;
        int r = ((it & 1) << 8) + tid;
        int ci = r >> 5, co = r & 31;
        ws[tap*640 + ci*40 + co] = g_wd0[((size_t)(tap*128 + ci))*128 + cb + co];
    }
    __syncthreads();

    for (int c0 = 0; c0 < 128; c0 += 16) {
        float4 pv4[3];
        float pw[18];
        bool nx = (c0 < 112);
        if (nx) {
            int cn = c0 + 16;
            #pragma unroll
            for (int it = 0; it < 3; it++) {
                int j = tid + it*256;
                pv4[it] = zero4;
                if (j < 624) {
                    int ci = j/39, r = j%39, y = r/13, q = r%13;
                    int ih = i0 + y;
                    if (ih < HH2)
                        pv4[it] = ((const float4*)g_qpack)[((size_t)((n*CCH + cn+ci)*HH2 + ih))*13 + q];
                }
            }
            #pragma unroll
            for (int it = 0; it < 18; it++) {
                int tap = it >> 1;
                int r = ((it & 1) << 8) + tid;
                int ci = r >> 5, co = r & 31;
                pw[it] = g_wd0[((size_t)(tap*128 + cn+ci))*128 + cb + co];
            }
        }
        #pragma unroll
        for (int ks = 0; ks < 2; ks++) {
            D0_STREAM(4, 0, 0, 0)
            D0_STREAM(3, 1, 0, 1)
            D0_STREAM(5, 1, 0, 0)
            D0_STREAM(1, 2, 1, 0)
            D0_STREAM(7, 2, 0, 0)
            D0_STREAM(0, 3, 1, 1)
            D0_STREAM(2, 3, 1, 0)
            D0_STREAM(6, 3, 0, 1)
            D0_STREAM(8, 3, 0, 0)
        }
        __syncthreads();
        if (nx) {
            #pragma unroll
            for (int it = 0; it < 3; it++) {
                int j = tid + it*256;
                if (j < 624) {
                    int ci = j/39, r = j%39, y = r/13, q = r%13;
                    *(float4*)&inp[ci*168 + y*56 + q*4] = pv4[it];
                }
            }
            #pragma unroll
            for (int it = 0; it < 18; it++) {
                int tap = it >> 1;
                int r = ((it & 1) << 8) + tid;
                int ci = r >> 5, co = r & 31;
                ws[tap*640 + ci*40 + co] = pw[it];
            }
            __syncthreads();
        }
    }
    int i = i0 + sub;
    int coA = cb + m0 + grp, coB = coA + 8;
    float bA = bias[coA], bB = bias[coB];
    float* pA = out + ((size_t)(n*CCH + coA))*HWX + (2*i)*WWW;
    float* pB = out + ((size_t)(n*CCH + coB))*HWX + (2*i)*WWW;
    #pragma unroll
    for (int nt = 0; nt < 3; nt++) {
        int j = half*24 + nt*8 + 2*qid;
        pA[2*j]       = acc[0][nt][0] + bA;  pA[2*j+1]     = acc[1][nt][0] + bA;
        pA[2*j+2]     = acc[0][nt][1] + bA;  pA[2*j+3]     = acc[1][nt][1] + bA;
        pA[WWW+2*j]   = acc[2][nt][0] + bA;  pA[WWW+2*j+1] = acc[3][nt][0] + bA;
        pA[WWW+2*j+2] = acc[2][nt][1] + bA;  pA[WWW+2*j+3] = acc[3][nt][1] + bA;
        pB[2*j]       = acc[0][nt][2] + bB;  pB[2*j+1]     = acc[1][nt][2] + bB;
        pB[2*j+2]     = acc[0][nt][3] + bB;  pB[2*j+3]     = acc[1][nt][3] + bB;
        pB[WWW+2*j]   = acc[2][nt][2] + bB;  pB[WWW+2*j+1] = acc[3][nt][2] + bB;
        pB[WWW+2*j+2] = acc[2][nt][3] + bB;  pB[WWW+2*j+3] = acc[3][nt][3] + bB;
    }
}

// ---------------- d1: tf32 MMA, pipelined ----------------
#define D1_SMEM_FLOATS (16*424 + 9*16*40)
__global__ void __launch_bounds__(256) conv_d1_mma_kernel(
        const float* __restrict__ wpack, const float* __restrict__ bias,
        float* __restrict__ out) {
    extern __shared__ float smem[];
    float* inh = smem;
    float* wsh = smem + 16*424;
    int oh0 = blockIdx.x*2, cb = blockIdx.y*32, n = blockIdx.z;
    int tid = threadIdx.x, lane = tid & 31, wid = tid >> 5;
    int row = (wid >> 2) & 1, m0 = ((wid >> 1) & 1)*16, half = wid & 1;
    int grp = lane >> 2, qid = lane & 3;
    float acc[6][4];
    #pragma unroll
    for (int i = 0; i < 6; i++)
        #pragma unroll
        for (int j = 0; j < 4; j++) acc[i][j] = 0.f;

    const float4 zero4 = make_float4(0.f, 0.f, 0.f, 0.f);
    for (int j = tid; j < 16*4*26; j += 256) {
        int ci = j/104, r = j%104, y = r/26, q = r%26;
        int ih = oh0 - 1 + y;
        float4 v = zero4;
        if (ih >= 0 && ih < 96)
            v = ((const float4*)g_dcomb)[((size_t)((n*256 + ci)*96 + ih))*26 + q];
        *(float4*)&inh[ci*424 + y*104 + q*4] = v;
    }
    #pragma unroll
    for (int it = 0; it < 18; it++) {
        int tap = it >> 1;
        int r = ((it & 1) << 8) + tid;
        int ci = r >> 5, co = r & 31;
        wsh[tap*640 + ci*40 + co] = wpack[((size_t)(tap*256 + ci))*128 + cb + co];
    }
    __syncthreads();

    for (int c0 = 0; c0 < 256; c0 += 16) {
        float4 pv4[7];
        float pw[18];
        bool nx = (c0 < 240);
        if (nx) {
            int cn = c0 + 16;
            #pragma unroll
            for (int it = 0; it < 7; it++) {
                int j = tid + it*256;
                pv4[it] = zero4;
                if (j < 1664) {
                    int ci = j/104, r = j%104, y = r/26, q = r%26;
                    int ih = oh0 - 1 + y;
                    if (ih >= 0 && ih < 96)
                        pv4[it] = ((const float4*)g_dcomb)[((size_t)((n*256 + cn+ci)*96 + ih))*26 + q];
                }
            }
            #pragma unroll
            for (int it = 0; it < 18; it++) {
                int tap = it >> 1;
                int r = ((it & 1) << 8) + tid;
                int ci = r >> 5, co = r & 31;
                pw[it] = wpack[((size_t)(tap*256 + cn+ci))*128 + cb + co];
            }
        }
        #pragma unroll
        for (int kh = 0; kh < 3; kh++) {
            #pragma unroll
            for (int kw = 0; kw < 3; kw++) {
                int tap = kh*3 + kw;
                #pragma unroll
                for (int ks = 0; ks < 2; ks++) {
                    int wb = tap*640 + (ks*8 + qid)*40 + m0 + grp;
                    float a0 = wsh[wb],     a1 = wsh[wb+8];
                    float a2 = wsh[wb+160], a3 = wsh[wb+168];
                    int bb = (ks*8 + qid)*424 + (row + kh)*104 + kw + half*48 + grp;
                    #pragma unroll
                    for (int nt = 0; nt < 6; nt++) {
                        float b0 = inh[bb + nt*8];
                        float b1 = inh[bb + 1696 + nt*8];
                        mma_tf32(acc[nt], a0, a1, a2, a3, b0, b1);
                    }
                }
            }
        }
        __syncthreads();
        if (nx) {
            #pragma unroll
            for (int it = 0; it < 7; it++) {
                int j = tid + it*256;
                if (j < 1664) {
                    int ci = j/104, r = j%104, y = r/26, q = r%26;
                    *(float4*)&inh[ci*424 + y*104 + q*4] = pv4[it];
                }
            }
            #pragma unroll
            for (int it = 0; it < 18; it++) {
                int tap = it >> 1;
                int r = ((it & 1) << 8) + tid;
                int ci = r >> 5, co = r & 31;
                wsh[tap*640 + ci*40 + co] = pw[it];
            }
            __syncthreads();
        }
    }
    int coA = cb + m0 + grp, coB = coA + 8;
    float bA = bias[coA], bB = bias[coB];
    int oh = oh0 + row;
    float* pA = out + ((size_t)(n*CCH + coA))*HWX + oh*WWW;
    float* pB = out + ((size_t)(n*CCH + coB))*HWX + oh*WWW;
    #pragma unroll
    for (int nt = 0; nt < 6; nt++) {
        int px = half*48 + nt*8 + 2*qid;
        pA[px]   = acc[nt][0] + bA;
        pA[px+1] = acc[nt][1] + bA;
        pB[px]   = acc[nt][2] + bB;
        pB[px+1] = acc[nt][3] + bB;
    }
}

// ---------------- ro: 1x1 128->4, fused d1-GN ----------------
__global__ void conv_ro_kernel(const float* __restrict__ y, const float* __restrict__ w,
                               const float* __restrict__ b, float* __restrict__ out,
                               const float* __restrict__ gam, const float* __restrict__ bet) {
    int t = blockIdx.x*256 + threadIdx.x;
    int n = t / HWX, p = t % HWX;
    __shared__ float ws[512];
    __shared__ float As[128], Bs[128];
    for (int j = threadIdx.x; j < 512; j += 256) ws[j] = w[j];
    if (threadIdx.x < 128) {
        int c = threadIdx.x;
        int ng = n*2 + (c >> 6);
        float mu = g_stats2[3][ng][0], rs = g_stats2[3][ng][1];
        float gm = gam[c];
        As[c] = rs*gm;
        Bs[c] = bet[c] - mu*rs*gm;
    }
    __syncthreads();
    if (t >= NNB*HWX) return;
    float a0 = b[0], a1 = b[1], a2 = b[2], a3 = b[3];
    const float* yp = y + (size_t)n*CCH*HWX + p;
    for (int ci = 0; ci < 128; ci++) {
        float v = yp[(size_t)ci*HWX];
        v = fmaf(v, As[ci], Bs[ci]);
        v = v >= 0.f ? v : SLOPE_F*v;
        a0 += v*ws[ci]; a1 += v*ws[128+ci]; a2 += v*ws[256+ci]; a3 += v*ws[384+ci];
    }
    out[((size_t)n*4 + 0)*HWX + p] = a0;
    out[((size_t)n*4 + 1)*HWX + p] = a1;
    out[((size_t)n*4 + 2)*HWX + p] = a2;
    out[((size_t)n*4 + 3)*HWX + p] = a3;
}

// ---------------- host ----------------
extern "C" void kernel_launch(void* const* d_in, const int* in_sizes, int n_in,
                              void* d_out, int out_size) {
    const float* x       = (const float*)d_in[0];
    const float* e0_w    = (const float*)d_in[1];
    const float* e0_b    = (const float*)d_in[2];
    const float* e0_g    = (const float*)d_in[3];
    const float* e0_beta = (const float*)d_in[4];
    const float* e1_w    = (const float*)d_in[5];
    const float* e1_b    = (const float*)d_in[6];
    const float* e1_g    = (const float*)d_in[7];
    const float* e1_beta = (const float*)d_in[8];
    const float* pv_w    = (const float*)d_in[9];
    const float* pv_b    = (const float*)d_in[10];
    const float* emb     = (const float*)d_in[11];
    const float* d0_w    = (const float*)d_in[12];
    const float* d0_b    = (const float*)d_in[13];
    const float* d0_g    = (const float*)d_in[14];
    const float* d0_beta = (const float*)d_in[15];
    const float* d1_w    = (const float*)d_in[16];
    const float* d1_b    = (const float*)d_in[17];
    const float* d1_g    = (const float*)d_in[18];
    const float* d1_beta = (const float*)d_in[19];
    const float* proj_w  = (const float*)d_in[20];
    const float* proj_b  = (const float*)d_in[21];
    const float* ro_w    = (const float*)d_in[22];
    const float* ro_b    = (const float*)d_in[23];
    float* out = (float*)d_out;

    float *bufA, *bufB, *zb, *hb, *yb, *wpk;
    cudaGetSymbolAddress((void**)&bufA, g_bufA);
    cudaGetSymbolAddress((void**)&bufB, g_bufB);
    cudaGetSymbolAddress((void**)&zb,   g_z);
    cudaGetSymbolAddress((void**)&hb,   g_h);
    cudaGetSymbolAddress((void**)&yb,   g_y);
    cudaGetSymbolAddress((void**)&wpk,  g_wpack);

    static cudaStream_t sA = nullptr, sB = nullptr;
    static cudaEvent_t evRoot = nullptr, evEnorm = nullptr, evStats0 = nullptr,
                       evSkip = nullptr, evTop3 = nullptr, evFin = nullptr;
    if (sA == nullptr) {
        cudaStreamCreateWithFlags(&sA, cudaStreamNonBlocking);
        cudaStreamCreateWithFlags(&sB, cudaStreamNonBlocking);
        cudaEventCreateWithFlags(&evRoot,   cudaEventDisableTiming);
        cudaEventCreateWithFlags(&evEnorm,  cudaEventDisableTiming);
        cudaEventCreateWithFlags(&evStats0, cudaEventDisableTiming);
        cudaEventCreateWithFlags(&evSkip,   cudaEventDisableTiming);
        cudaEventCreateWithFlags(&evTop3,   cudaEventDisableTiming);
        cudaEventCreateWithFlags(&evFin,    cudaEventDisableTiming);
        cudaFuncSetAttribute(conv_e1_mma_kernel, cudaFuncAttributeMaxDynamicSharedMemorySize,
                             E1_SMEM_FLOATS*4);
        cudaFuncSetAttribute(conv_d0_mma_kernel, cudaFuncAttributeMaxDynamicSharedMemorySize,
                             D0_SMEM_FLOATS*4);
        cudaFuncSetAttribute(conv_d1_mma_kernel, cudaFuncAttributeMaxDynamicSharedMemorySize,
                             D1_SMEM_FLOATS*4);
    }

    // fork point
    cudaEventRecord(evRoot, 0);

    // streamB: emb norms (independent)
    cudaStreamWaitEvent(sB, evRoot, 0);
    enorm_kernel<<<CODES/8, 256, 0, sB>>>(emb);
    cudaEventRecord(evEnorm, sB);

    // main: init/pack + encoder stage 0 + GN0 stats
    init_pack_kernel<<<(9*256*128+255)/256, 256>>>(d1_w, d0_w, e1_w);
    conv_e0_kernel<<<dim3(48,4,2), 192>>>(x, e0_w, e0_b, bufA);
    gn_part_kernel<<<dim3(8,64), 256>>>(bufA, HWX, 0);
    cudaEventRecord(evStats0, 0);

    // streamA: skip path concurrent with e1/pv/scores
    cudaStreamWaitEvent(sA, evStats0, 0);
    skip_mma_kernel<<<dim3(96,4), 256, 0, sA>>>(bufA, proj_w, proj_b, e0_g, e0_beta);
    cudaEventRecord(evSkip, sA);

    // main: prep_e1 -> e1 -> GN1 -> pv
    prep_e1_kernel<<<NNB*CCH*96/8, 256>>>(bufA, e0_g, e0_beta);
    conv_e1_mma_kernel<<<dim3(24,4,4), 256, E1_SMEM_FLOATS*4>>>(e1_b, bufB);
    gn_part_kernel<<<dim3(8,64), 256>>>(bufB, HW2, 1);
    pv_mma_kernel<<<dim3(24,2,4), 256>>>(bufB, pv_w, pv_b, e1_g, e1_beta, zb);

    // main: VQ
    cudaStreamWaitEvent(0, evEnorm, 0);
    scores_mma_kernel<<<dim3(72,8), 256>>>(emb, zb);
    top3_merge_kernel<<<ROWS/256, 256>>>();
    cudaEventRecord(evTop3, 0);

    // streamB: loss + perplexity concurrent with decoder
    cudaStreamWaitEvent(sB, evTop3, 0);
    loss_part_kernel<<<36, 256, 0, sB>>>(emb, zb);
    finalize_kernel<<<1, 1024, 0, sB>>>(out, out + (out_size - 1));
    cudaEventRecord(evFin, sB);

    // main: decoder
    prep_q_kernel<<<NNB*CCH*HH2/8, 256>>>(emb);
    conv_d0_mma_kernel<<<dim3(24,4,4), 256, D0_SMEM_FLOATS*4>>>(d0_b, hb);
    gn_part_kernel<<<dim3(8,64), 256>>>(hb, HWX, 2);
    prep_d_kernel<<<NNB*CCH*96/8, 256>>>(hb, d0_g, d0_beta);

    cudaStreamWaitEvent(0, evSkip, 0);
    conv_d1_mma_kernel<<<dim3(48,4,4), 256, D1_SMEM_FLOATS*4>>>(wpk, d1_b, yb);
    gn_part_kernel<<<dim3(8,64), 256>>>(yb, HWX, 3);

    cudaStreamWaitEvent(0, evFin, 0);
    conv_ro_kernel<<<NNB*HWX/256, 256>>>(yb, ro_w, ro_b, out + 1, d1_g, d1_beta);
}

// round 15
// speedup vs baseline: 1.0391x; 1.0170x over previous
#include <cuda_runtime.h>
#include <math.h>
#include <stdint.h>

#define NNB 4
#define CCH 128
#define HHH 96
#define WWW 96
#define HWX 9216
#define HH2 48
#define HW2 2304
#define ROWS 9216
#define CODES 1024
#define GN_EPS_F 1e-5f
#define SLOPE_F 0.2f

// ---------------- scratch ----------------
__device__ float g_bufA[NNB*CCH*HWX];
__device__ float g_bufB[NNB*CCH*HW2];
__device__ float g_z[NNB*CCH*HW2];
__device__ float g_h[NNB*CCH*HWX];
__device__ float g_y[NNB*CCH*HWX];
__device__ float g_e1h[NNB*CCH*96*104];
__device__ float g_e1l[NNB*CCH*96*104];
__device__ float g_dcomb[NNB*256*96*104];
__device__ float g_qpack[NNB*CCH*HH2*52];
__device__ float g_wpack[9*256*128];
__device__ float g_wd0[9*128*128];
__device__ float g_we1h[9*128*128];
__device__ float g_we1l[9*128*128];
__device__ float g_pv[ROWS*24];
__device__ int   g_pi[ROWS*24];
__device__ float g_en2[CODES];
__device__ float g_part[8*64*2];
__device__ float g_stats2[4][8][2];
__device__ float g_losspart[36];
__device__ int   g_idx0[ROWS];
__device__ int   g_counts[CODES];
__device__ int   g_ticket[16];

__device__ __forceinline__ float to_tf32(float v) {
    uint32_t u;
    asm("cvt.rna.tf32.f32 %0, %1;" : "=r"(u) : "f"(v));
    return __uint_as_float(u);
}

__device__ __forceinline__ void mma_tf32(float c[4], float a0, float a1, float a2, float a3,
                                         float b0, float b1) {
    uint32_t A0 = __float_as_uint(a0), A1 = __float_as_uint(a1);
    uint32_t A2 = __float_as_uint(a2), A3 = __float_as_uint(a3);
    uint32_t B0 = __float_as_uint(b0), B1 = __float_as_uint(b1);
    asm volatile(
        "mma.sync.aligned.m16n8k8.row.col.f32.tf32.tf32.f32 "
        "{%0,%1,%2,%3},{%4,%5,%6,%7},{%8,%9},{%0,%1,%2,%3};\n"
        : "+f"(c[0]), "+f"(c[1]), "+f"(c[2]), "+f"(c[3])
        : "r"(A0), "r"(A1), "r"(A2), "r"(A3), "r"(B0), "r"(B1));
}

// ---------------- combined init + weight packing ----------------
__global__ void init_pack_kernel(const float* __restrict__ d1w, const float* __restrict__ d0w,
                                 const float* __restrict__ e1w) {
    int t = blockIdx.x*256 + threadIdx.x;
    if (t < CODES) g_counts[t] = 0;
    if (t < 16) g_ticket[t] = 0;
    if (t < 9*256*128) {
        int co = t & 127, ci = (t >> 7) & 255, tap = t >> 15;
        g_wpack[((size_t)tap*256 + ci)*128 + co] = to_tf32(d1w[((size_t)co*256 + ci)*9 + tap]);
    }
    if (t < 9*128*128) {
        int co = t & 127, ci = (t >> 7) & 127, tap = t >> 14;
        g_wd0[((size_t)tap*128 + ci)*128 + co] = to_tf32(d0w[((size_t)ci*128 + co)*9 + tap]);
        float v = e1w[((size_t)co*128 + ci)*9 + tap];
        float h = to_tf32(v);
        g_we1h[((size_t)tap*128 + ci)*128 + co] = h;
        g_we1l[((size_t)tap*128 + ci)*128 + co] = to_tf32(v - h);
    }
}

// ---------------- e0: conv3x3 s1 p1, 4->128 ----------------
__global__ void __launch_bounds__(192) conv_e0_kernel(const float* __restrict__ x,
                                                      const float* __restrict__ w,
                                                      const float* __restrict__ b,
                                                      float* __restrict__ out, int n0) {
    int n = n0 + blockIdx.z;
    int oh0 = blockIdx.x*2, ch = blockIdx.y*64;
    __shared__ float xs[4][4][98];
    __shared__ float ws[36*64];
    int tid = threadIdx.x;
    for (int j = tid; j < 4*4*98; j += 192) {
        int ci = j/392, r2 = j%392, y = r2/98, xx = r2%98;
        int ih = oh0 - 1 + y, iw = xx - 1;
        float v = 0.f;
        if (ih >= 0 && ih < HHH && iw >= 0 && iw < WWW)
            v = x[((size_t)(n*4 + ci))*HWX + ih*WWW + iw];
        xs[ci][y][xx] = v;
    }
    for (int j = tid; j < 36*64; j += 192) {
        int tap = j >> 6, co = j & 63;
        ws[j] = w[(ch + co)*36 + tap];
    }
    __syncthreads();
    int r = tid/96, ow = tid%96, oh = oh0 + r;
    float iv[36];
    #pragma unroll
    for (int ci = 0; ci < 4; ci++)
        #pragma unroll
        for (int kh = 0; kh < 3; kh++)
            #pragma unroll
            for (int kw = 0; kw < 3; kw++)
                iv[ci*9 + kh*3 + kw] = xs[ci][r + kh][ow + kw];
    for (int co0 = 0; co0 < 64; co0 += 4) {
        float4 acc = *(const float4*)&b[ch + co0];
        #pragma unroll
        for (int tap = 0; tap < 36; tap++) {
            float4 wv = *(const float4*)&ws[tap*64 + co0];
            acc.x += iv[tap]*wv.x; acc.y += iv[tap]*wv.y;
            acc.z += iv[tap]*wv.z; acc.w += iv[tap]*wv.w;
        }
        float* op = out + ((size_t)(n*CCH + ch + co0))*HWX + oh*WWW + ow;
        op[0] = acc.x; op[HWX] = acc.y; op[2*HWX] = acc.z; op[3*HWX] = acc.w;
    }
}

// ---------------- GroupNorm stats: per-(stage,n) ticket ----------------
__global__ void gn_part_kernel(const float* __restrict__ buf, int hw, int stage, int n0) {
    int n = n0 + blockIdx.z;
    int gl = blockIdx.x;
    int bb = blockIdx.y;
    int ng = n*2 + gl;
    const float4* p4 = (const float4*)(buf + ((size_t)n*CCH + gl*64)*hw);
    int len4 = 16*hw;
    float s = 0.f, ss = 0.f;
    for (int i = bb*256 + threadIdx.x; i < len4; i += 64*256) {
        float4 v = p4[i];
        s += (v.x + v.y) + (v.z + v.w);
        ss += v.x*v.x + v.y*v.y + v.z*v.z + v.w*v.w;
    }
    __shared__ float sh[256], sh2[256];
    __shared__ int flag;
    sh[threadIdx.x] = s; sh2[threadIdx.x] = ss; __syncthreads();
    for (int o = 128; o; o >>= 1) {
        if (threadIdx.x < o) { sh[threadIdx.x] += sh[threadIdx.x+o]; sh2[threadIdx.x] += sh2[threadIdx.x+o]; }
        __syncthreads();
    }
    if (threadIdx.x == 0) {
        g_part[(ng*64+bb)*2] = sh[0]; g_part[(ng*64+bb)*2+1] = sh2[0];
        __threadfence();
        int done = atomicAdd(&g_ticket[stage*4 + n], 1);
        flag = (done == 127);
    }
    __syncthreads();
    if (flag && threadIdx.x < 2) {
        int g2 = n*2 + threadIdx.x;
        float s2 = 0.f, ss2 = 0.f;
        for (int b2 = 0; b2 < 64; b2++) { s2 += g_part[(g2*64+b2)*2]; ss2 += g_part[(g2*64+b2)*2+1]; }
        float cnt = 64.f * (float)hw;
        float mu  = s2 / cnt;
        float var = ss2 / cnt - mu*mu;
        g_stats2[stage][g2][0] = mu; g_stats2[stage][g2][1] = rsqrtf(var + GN_EPS_F);
    }
}

// ---------------- prep_e1 ----------------
__global__ void __launch_bounds__(256) prep_e1_kernel(const float* __restrict__ in,
                                                      const float* __restrict__ gam,
                                                      const float* __restrict__ bet, int n0) {
    int n = n0 + blockIdx.y;
    int gw = blockIdx.x*8 + (threadIdx.x >> 5);
    int lane = threadIdx.x & 31;
    int ih = gw % 96; int ci = gw / 96;
    int ng = n*2 + (ci >> 6);
    float rs = g_stats2[0][ng][1], mu = g_stats2[0][ng][0];
    float A = rs*gam[ci];
    float B = bet[ci] - mu*A;
    const float* src = in + ((size_t)(n*CCH + ci))*HWX + ih*WWW;
    float* dh = g_e1h + (size_t)(n*12288 + gw)*104;
    float* dl = g_e1l + (size_t)(n*12288 + gw)*104;
    #pragma unroll
    for (int r = 0; r < 3; r++) {
        int iw = lane + r*32;
        float v = src[iw];
        v = fmaf(v, A, B);
        v = v >= 0.f ? v : SLOPE_F*v;
        float h = to_tf32(v);
        int dst = (iw & 1) ? ((iw+1) >> 1) : (52 + (iw >> 1));
        dh[dst] = h; dl[dst] = to_tf32(v - h);
    }
    if (lane == 0) { dh[0] = 0.f; dl[0] = 0.f; }
}

// ---------------- prep_d ----------------
__global__ void __launch_bounds__(256) prep_d_kernel(const float* __restrict__ in,
                                                     const float* __restrict__ gam,
                                                     const float* __restrict__ bet, int n0) {
    int n = n0 + blockIdx.y;
    int gw = blockIdx.x*8 + (threadIdx.x >> 5);
    int lane = threadIdx.x & 31;
    int ih = gw % 96; int ci = gw / 96;
    int ng = n*2 + (ci >> 6);
    float rs = g_stats2[2][ng][1], mu = g_stats2[2][ng][0];
    float A = rs*gam[ci];
    float B = bet[ci] - mu*A;
    const float* src = in + ((size_t)(n*CCH + ci))*HWX + ih*WWW;
    float* dst = g_dcomb + ((size_t)((n*256 + ci)*96 + ih))*104;
    #pragma unroll
    for (int r = 0; r < 3; r++) {
        int iw = lane + r*32;
        float v = src[iw];
        v = fmaf(v, A, B);
        v = v >= 0.f ? v : SLOPE_F*v;
        dst[iw + 1] = to_tf32(v);
    }
    if (lane == 0) dst[0] = 0.f;
    if (lane < 7) dst[97 + lane] = 0.f;
}

// ---------------- prep_q ----------------
__global__ void __launch_bounds__(256) prep_q_kernel(const float* __restrict__ emb, int n0) {
    int n = n0 + blockIdx.y;
    int gw = blockIdx.x*8 + (threadIdx.x >> 5);
    int lane = threadIdx.x & 31;
    int ih = gw % HH2; int ci = gw / HH2;
    const int* idx = g_idx0 + n*HW2 + ih*HH2;
    float* dst = g_qpack + (size_t)(n*6144 + gw)*52;
    dst[lane] = to_tf32(emb[(size_t)idx[lane]*CCH + ci]);
    if (lane < 16) dst[32 + lane] = to_tf32(emb[(size_t)idx[32 + lane]*CCH + ci]);
    if (lane < 4) dst[48 + lane] = 0.f;
}

// ---------------- e1: split-tf32 MMA, pipelined ----------------
#define E1_SMEM_FLOATS (4160+4160+2880+2880)
__global__ void __launch_bounds__(256) conv_e1_mma_kernel(
        const float* __restrict__ bias, float* __restrict__ out, int n0) {
    extern __shared__ float smem[];
    float* inh = smem;
    float* inl = smem + 4160;
    float* wsh = smem + 8320;
    float* wsl = smem + 11200;
    int n = n0 + blockIdx.z;
    int oh0 = blockIdx.x*2, cb = blockIdx.y*32;
    int tid = threadIdx.x, lane = tid & 31, wid = tid >> 5;
    int row = (wid >> 2) & 1, m0 = ((wid >> 1) & 1)*16, half = wid & 1;
    int grp = lane >> 2, qid = lane & 3;
    float acc[3][4];
    #pragma unroll
    for (int i = 0; i < 3; i++)
        #pragma unroll
        for (int j = 0; j < 4; j++) acc[i][j] = 0.f;

    const float4 zero4 = make_float4(0.f, 0.f, 0.f, 0.f);
    for (int j = tid; j < 8*5*26; j += 256) {
        int ci = j/130, r = j%130, y = r/26, q = r%26;
        int ih = 2*oh0 - 1 + y;
        float4 vh = zero4, vl = zero4;
        if (ih >= 0 && ih < 96) {
            size_t srow = ((size_t)((n*CCH + ci)*96 + ih))*26 + q;
            vh = ((const float4*)g_e1h)[srow];
            vl = ((const float4*)g_e1l)[srow];
        }
        *(float4*)&inh[ci*520 + y*104 + q*4] = vh;
        *(float4*)&inl[ci*520 + y*104 + q*4] = vl;
    }
    {
        int ciw = tid >> 5, cow = tid & 31;
        #pragma unroll
        for (int it = 0; it < 9; it++) {
            size_t src = ((size_t)(it*128 + ciw))*128 + cb + cow;
            int dst = it*320 + ciw*40 + cow;
            wsh[dst] = g_we1h[src];
            wsl[dst] = g_we1l[src];
        }
    }
    __syncthreads();

    for (int c0 = 0; c0 < 128; c0 += 8) {
        float4 ph[5], pl[5];
        float pwh[9], pwl[9];
        bool nx = (c0 < 120);
        if (nx) {
            int cn = c0 + 8;
            #pragma unroll
            for (int it = 0; it < 5; it++) {
                int j = tid + it*256;
                ph[it] = zero4; pl[it] = zero4;
                if (j < 1040) {
                    int ci = j/130, r = j%130, y = r/26, q = r%26;
                    int ih = 2*oh0 - 1 + y;
                    if (ih >= 0 && ih < 96) {
                        size_t srow = ((size_t)((n*CCH + cn+ci)*96 + ih))*26 + q;
                        ph[it] = ((const float4*)g_e1h)[srow];
                        pl[it] = ((const float4*)g_e1l)[srow];
                    }
                }
            }
            int ciw = tid >> 5, cow = tid & 31;
            #pragma unroll
            for (int it = 0; it < 9; it++) {
                size_t src = ((size_t)(it*128 + cn+ciw))*128 + cb + cow;
                pwh[it] = g_we1h[src];
                pwl[it] = g_we1l[src];
            }
        }
        #pragma unroll
        for (int kh = 0; kh < 3; kh++) {
            #pragma unroll
            for (int kw = 0; kw < 3; kw++) {
                int tap = kh*3 + kw;
                int wb = tap*320 + qid*40 + m0 + grp;
                float ah0 = wsh[wb],     ah1 = wsh[wb+8];
                float ah2 = wsh[wb+160], ah3 = wsh[wb+168];
                float al0 = wsl[wb],     al1 = wsl[wb+8];
                float al2 = wsl[wb+160], al3 = wsl[wb+168];
                int bb = qid*520 + (2*row + kh)*104 + (kw & 1)*52 + (kw >> 1) + half*24 + grp;
                #pragma unroll
                for (int nt = 0; nt < 3; nt++) {
                    float bh0 = inh[bb + nt*8], bh1 = inh[bb + 2080 + nt*8];
                    float bl0 = inl[bb + nt*8], bl1 = inl[bb + 2080 + nt*8];
                    mma_tf32(acc[nt], ah0, ah1, ah2, ah3, bh0, bh1);
                    mma_tf32(acc[nt], ah0, ah1, ah2, ah3, bl0, bl1);
                    mma_tf32(acc[nt], al0, al1, al2, al3, bh0, bh1);
                }
            }
        }
        __syncthreads();
        if (nx) {
            #pragma unroll
            for (int it = 0; it < 5; it++) {
                int j = tid + it*256;
                if (j < 1040) {
                    int ci = j/130, r = j%130, y = r/26, q = r%26;
                    *(float4*)&inh[ci*520 + y*104 + q*4] = ph[it];
                    *(float4*)&inl[ci*520 + y*104 + q*4] = pl[it];
                }
            }
            int ciw = tid >> 5, cow = tid & 31;
            #pragma unroll
            for (int it = 0; it < 9; it++) {
                int dst = it*320 + ciw*40 + cow;
                wsh[dst] = pwh[it];
                wsl[dst] = pwl[it];
            }
            __syncthreads();
        }
    }
    int coA = cb + m0 + grp, coB = coA + 8;
    float bA = bias[coA], bB = bias[coB];
    int oh = oh0 + row;
    float* pA = out + ((size_t)(n*CCH + coA))*HW2 + oh*HH2;
    float* pB = out + ((size_t)(n*CCH + coB))*HW2 + oh*HH2;
    #pragma unroll
    for (int nt = 0; nt < 3; nt++) {
        int px = half*24 + nt*8 + 2*qid;
        pA[px]   = acc[nt][0] + bA;
        pA[px+1] = acc[nt][1] + bA;
        pB[px]   = acc[nt][2] + bB;
        pB[px+1] = acc[nt][3] + bB;
    }
}

// ---------------- pv: 1x1 split-tf32 MMA, pipelined ----------------
__global__ void __launch_bounds__(256) pv_mma_kernel(
        const float* __restrict__ in, const float* __restrict__ w,
        const float* __restrict__ bias, const float* __restrict__ gam,
        const float* __restrict__ bet, float* __restrict__ out, int n0) {
    __shared__ float inh[16*104], inl[16*104], wh[16*72], wl[16*72];
    __shared__ float As[128], Bs[128];
    int n = n0 + blockIdx.z;
    int pt = blockIdx.x*96, cb = blockIdx.y*64;
    int tid = threadIdx.x, lane = tid & 31, wid = tid >> 5;
    int half = wid >> 2, m0 = (wid & 3)*16;
    int grp = lane >> 2, qid = lane & 3;
    if (tid < 128) {
        int ng = n*2 + (tid >> 6);
        float mu = g_stats2[1][ng][0], rs = g_stats2[1][ng][1];
        float gm = gam[tid];
        As[tid] = rs*gm;
        Bs[tid] = bet[tid] - mu*rs*gm;
    }
    __syncthreads();
    float acc[6][4];
    #pragma unroll
    for (int i = 0; i < 6; i++)
        #pragma unroll
        for (int j = 0; j < 4; j++) acc[i][j] = 0.f;

    #pragma unroll
    for (int it = 0; it < 6; it++) {
        int j = tid + it*256;
        int k = j/96, px = j%96;
        float v = in[((size_t)(n*CCH + k))*HW2 + pt + px];
        v = fmaf(v, As[k], Bs[k]);
        v = v >= 0.f ? v : SLOPE_F*v;
        float h = to_tf32(v);
        inh[k*104 + px] = h; inl[k*104 + px] = to_tf32(v - h);
    }
    #pragma unroll
    for (int it = 0; it < 4; it++) {
        int j = tid + it*256;
        int k = j >> 6, co = j & 63;
        float v = w[(size_t)(cb+co)*128 + k];
        float h = to_tf32(v);
        wh[k*72 + co] = h; wl[k*72 + co] = to_tf32(v - h);
    }
    __syncthreads();

    for (int c0 = 0; c0 < 128; c0 += 16) {
        float pin[6], pwv[4];
        bool nx = (c0 < 112);
        if (nx) {
            int cn = c0 + 16;
            #pragma unroll
            for (int it = 0; it < 6; it++) {
                int j = tid + it*256;
                int k = j/96, px = j%96;
                pin[it] = in[((size_t)(n*CCH + cn+k))*HW2 + pt + px];
            }
            #pragma unroll
            for (int it = 0; it < 4; it++) {
                int j = tid + it*256;
                int k = j >> 6, co = j & 63;
                pwv[it] = w[(size_t)(cb+co)*128 + cn + k];
            }
        }
        #pragma unroll
        for (int ks = 0; ks < 2; ks++) {
            int wb = (ks*8 + qid)*72 + m0 + grp;
            float ah0 = wh[wb], ah1 = wh[wb+8], ah2 = wh[wb+288], ah3 = wh[wb+296];
            float al0 = wl[wb], al1 = wl[wb+8], al2 = wl[wb+288], al3 = wl[wb+296];
            int bb = (ks*8 + qid)*104 + half*48 + grp;
            #pragma unroll
            for (int nt = 0; nt < 6; nt++) {
                float bh0 = inh[bb + nt*8], bh1 = inh[bb + 416 + nt*8];
                float bl0 = inl[bb + nt*8], bl1 = inl[bb + 416 + nt*8];
                mma_tf32(acc[nt], ah0, ah1, ah2, ah3, bh0, bh1);
                mma_tf32(acc[nt], ah0, ah1, ah2, ah3, bl0, bl1);
                mma_tf32(acc[nt], al0, al1, al2, al3, bh0, bh1);
            }
        }
        __syncthreads();
        if (nx) {
            int cn = c0 + 16;
            #pragma unroll
            for (int it = 0; it < 6; it++) {
                int j = tid + it*256;
                int k = j/96, px = j%96;
                float v = fmaf(pin[it], As[cn+k], Bs[cn+k]);
                v = v >= 0.f ? v : SLOPE_F*v;
                float h = to_tf32(v);
                inh[k*104 + px] = h; inl[k*104 + px] = to_tf32(v - h);
            }
            #pragma unroll
            for (int it = 0; it < 4; it++) {
                int j = tid + it*256;
                int k = j >> 6, co = j & 63;
                float h = to_tf32(pwv[it]);
                wh[k*72 + co] = h; wl[k*72 + co] = to_tf32(pwv[it] - h);
            }
            __syncthreads();
        }
    }
    int coA = cb + m0 + grp, coB = coA + 8;
    float bA = bias[coA], bB = bias[coB];
    float* pA = out + ((size_t)(n*CCH + coA))*HW2 + pt;
    float* pB = out + ((size_t)(n*CCH + coB))*HW2 + pt;
    #pragma unroll
    for (int nt = 0; nt < 6; nt++) {
        int px = half*48 + nt*8 + 2*qid;
        pA[px]   = acc[nt][0] + bA;
        pA[px+1] = acc[nt][1] + bA;
        pB[px]   = acc[nt][2] + bB;
        pB[px+1] = acc[nt][3] + bB;
    }
}

// ---------------- skip: 1x1 tf32 MMA, pipelined, writes g_dcomb ----------------
__global__ void __launch_bounds__(256) skip_mma_kernel(
        const float* __restrict__ in, const float* __restrict__ w,
        const float* __restrict__ bias, const float* __restrict__ gam,
        const float* __restrict__ bet, int n0) {
    __shared__ float inh[16*104], wh[16*136];
    __shared__ float As[128], Bs[128];
    int n = n0 + blockIdx.y;
    int oh = blockIdx.x;
    int pt = oh*96;
    int tid = threadIdx.x, lane = tid & 31, wid = tid >> 5;
    int m0 = wid*16;
    int grp = lane >> 2, qid = lane & 3;
    if (tid < 128) {
        int ng = n*2 + (tid >> 6);
        float mu = g_stats2[0][ng][0], rs = g_stats2[0][ng][1];
        float gm = gam[tid];
        As[tid] = rs*gm;
        Bs[tid] = bet[tid] - mu*rs*gm;
    }
    for (int j = tid; j < 128*8; j += 256) {
        int co = j >> 3, c = j & 7;
        int col = (c == 0) ? 0 : 96 + c;
        g_dcomb[((size_t)((n*256 + 128 + co)*96 + oh))*104 + col] = 0.f;
    }
    __syncthreads();
    float acc[12][4];
    #pragma unroll
    for (int i = 0; i < 12; i++)
        #pragma unroll
        for (int j = 0; j < 4; j++) acc[i][j] = 0.f;

    #pragma unroll
    for (int it = 0; it < 6; it++) {
        int j = tid + it*256;
        int k = j/96, px = j%96;
        float v = in[((size_t)(n*CCH + k))*HWX + pt + px];
        v = fmaf(v, As[k], Bs[k]);
        v = v >= 0.f ? v : SLOPE_F*v;
        inh[k*104 + px] = to_tf32(v);
    }
    #pragma unroll
    for (int it = 0; it < 8; it++) {
        int j = tid + it*256;
        int k = j & 15, co = j >> 4;
        wh[k*136 + co] = to_tf32(w[(size_t)co*128 + k]);
    }
    __syncthreads();

    for (int c0 = 0; c0 < 128; c0 += 16) {
        float pin[6], pwv[8];
        bool nx = (c0 < 112);
        if (nx) {
            int cn = c0 + 16;
            #pragma unroll
            for (int it = 0; it < 6; it++) {
                int j = tid + it*256;
                int k = j/96, px = j%96;
                pin[it] = in[((size_t)(n*CCH + cn+k))*HWX + pt + px];
            }
            #pragma unroll
            for (int it = 0; it < 8; it++) {
                int j = tid + it*256;
                int k = j & 15, co = j >> 4;
                pwv[it] = w[(size_t)co*128 + cn + k];
            }
        }
        #pragma unroll
        for (int ks = 0; ks < 2; ks++) {
            int wb = (ks*8 + qid)*136 + m0 + grp;
            float a0 = wh[wb], a1 = wh[wb+8], a2 = wh[wb+544], a3 = wh[wb+552];
            int bb = (ks*8 + qid)*104 + grp;
            #pragma unroll
            for (int nt = 0; nt < 12; nt++) {
                float b0 = inh[bb + nt*8], b1 = inh[bb + 416 + nt*8];
                mma_tf32(acc[nt], a0, a1, a2, a3, b0, b1);
            }
        }
        __syncthreads();
        if (nx) {
            int cn = c0 + 16;
            #pragma unroll
            for (int it = 0; it < 6; it++) {
                int j = tid + it*256;
                int k = j/96, px = j%96;
                float v = fmaf(pin[it], As[cn+k], Bs[cn+k]);
                v = v >= 0.f ? v : SLOPE_F*v;
                inh[k*104 + px] = to_tf32(v);
            }
            #pragma unroll
            for (int it = 0; it < 8; it++) {
                int j = tid + it*256;
                int k = j & 15, co = j >> 4;
                wh[k*136 + co] = to_tf32(pwv[it]);
            }
            __syncthreads();
        }
    }
    int coA = m0 + grp, coB = coA + 8;
    float bA = bias[coA], bB = bias[coB];
    float* pA = g_dcomb + ((size_t)((n*256 + 128 + coA)*96 + oh))*104 + 1;
    float* pB = g_dcomb + ((size_t)((n*256 + 128 + coB)*96 + oh))*104 + 1;
    #pragma unroll
    for (int nt = 0; nt < 12; nt++) {
        int px = nt*8 + 2*qid;
        pA[px]   = to_tf32(acc[nt][0] + bA);
        pA[px+1] = to_tf32(acc[nt][1] + bA);
        pB[px]   = to_tf32(acc[nt][2] + bB);
        pB[px+1] = to_tf32(acc[nt][3] + bB);
    }
}

// ---------------- emb norms ----------------
__global__ void enorm_kernel(const float* __restrict__ emb) {
    int wp = (blockIdx.x*256 + threadIdx.x) >> 5;
    int lane = threadIdx.x & 31;
    if (wp >= CODES) return;
    const float* e = emb + (size_t)wp*CCH;
    float s = 0.f;
    for (int d = lane; d < CCH; d += 32) { float v = e[d]; s += v*v; }
    for (int o = 16; o; o >>= 1) s += __shfl_down_sync(0xffffffffu, s, o);
    if (lane == 0) g_en2[wp] = s;
}

// ---------------- top3 insert ----------------
__device__ __forceinline__ void topk_insert(float v, int i,
        float& v0, int& i0, float& v1, int& i1, float& v2, int& i2) {
    bool b2 = (v < v2) || (v == v2 && i < i2);
    if (!b2) return;
    bool b1 = (v < v1) || (v == v1 && i < i1);
    bool b0 = (v < v0) || (v == v0 && i < i0);
    if (b0)      { v2=v1;i2=i1; v1=v0;i1=i0; v0=v;i0=i; }
    else if (b1) { v2=v1;i2=i1; v1=v; i1=i; }
    else         { v2=v; i2=i; }
}

// ---------------- scores: split-tf32 MMA + fused partial top3 ----------------
__global__ void __launch_bounds__(256) scores_mma_kernel(const float* __restrict__ emb,
                                                         const float* __restrict__ z, int n0) {
    __shared__ float zh[16*136], zl[16*136], eh[16*136], el[16*136];
    int n = n0 + blockIdx.z;
    int p0 = blockIdx.x*128;
    int r0 = n*HW2 + p0;
    int c0 = blockIdx.y*128;
    int tid = threadIdx.x, lane = tid & 31, wid = tid >> 5;
    int m0 = wid*16;
    int grp = lane >> 2, qid = lane & 3;
    float acc[16][4];
    #pragma unroll
    for (int i = 0; i < 16; i++)
        #pragma unroll
        for (int j = 0; j < 4; j++) acc[i][j] = 0.f;

    #pragma unroll
    for (int it = 0; it < 8; it++) {
        int j = tid + it*256;
        int k = j >> 7, row = j & 127;
        float v = z[((size_t)(n*CCH + k))*HW2 + p0 + row];
        float h = to_tf32(v);
        zh[k*136 + row] = h; zl[k*136 + row] = to_tf32(v - h);
    }
    #pragma unroll
    for (int it = 0; it < 8; it++) {
        int j = tid + it*256;
        int cd = j >> 4, k = j & 15;
        float v = emb[(size_t)(c0+cd)*CCH + k];
        float h = to_tf32(v);
        eh[k*136 + cd] = h; el[k*136 + cd] = to_tf32(v - h);
    }
    __syncthreads();

    for (int k0 = 0; k0 < 128; k0 += 16) {
        float pz[8], pe[8];
        bool nx = (k0 < 112);
        if (nx) {
            int kn = k0 + 16;
            #pragma unroll
            for (int it = 0; it < 8; it++) {
                int j = tid + it*256;
                int k = j >> 7, row = j & 127;
                pz[it] = z[((size_t)(n*CCH + kn + k))*HW2 + p0 + row];
            }
            #pragma unroll
            for (int it = 0; it < 8; it++) {
                int j = tid + it*256;
                int cd = j >> 4, k = j & 15;
                pe[it] = emb[(size_t)(c0+cd)*CCH + kn + k];
            }
        }
        #pragma unroll
        for (int ks = 0; ks < 2; ks++) {
            int wb = (ks*8 + qid)*136 + m0 + grp;
            float ah0 = zh[wb], ah1 = zh[wb+8], ah2 = zh[wb+544], ah3 = zh[wb+552];
            float al0 = zl[wb], al1 = zl[wb+8], al2 = zl[wb+544], al3 = zl[wb+552];
            int bb = (ks*8 + qid)*136 + grp;
            #pragma unroll
            for (int nt = 0; nt < 16; nt++) {
                float bh0 = eh[bb + nt*8], bh1 = eh[bb + 544 + nt*8];
                float bl0 = el[bb + nt*8], bl1 = el[bb + 544 + nt*8];
                mma_tf32(acc[nt], ah0, ah1, ah2, ah3, bh0, bh1);
                mma_tf32(acc[nt], ah0, ah1, ah2, ah3, bl0, bl1);
                mma_tf32(acc[nt], al0, al1, al2, al3, bh0, bh1);
            }
        }
        __syncthreads();
        if (nx) {
            #pragma unroll
            for (int it = 0; it < 8; it++) {
                int j = tid + it*256;
                int k = j >> 7, row = j & 127;
                float h = to_tf32(pz[it]);
                zh[k*136 + row] = h; zl[k*136 + row] = to_tf32(pz[it] - h);
            }
            #pragma unroll
            for (int it = 0; it < 8; it++) {
                int j = tid + it*256;
                int cd = j >> 4, k = j & 15;
                float h = to_tf32(pe[it]);
                eh[k*136 + cd] = h; el[k*136 + cd] = to_tf32(pe[it] - h);
            }
            __syncthreads();
        }
    }
    const float FMAXV = 3.402823466e38f;
    float av0 = FMAXV, av1 = FMAXV, av2 = FMAXV;
    float bv0 = FMAXV, bv1 = FMAXV, bv2 = FMAXV;
    int ai0 = 0x7fffffff, ai1 = 0x7fffffff, ai2 = 0x7fffffff;
    int bi0 = 0x7fffffff, bi1 = 0x7fffffff, bi2 = 0x7fffffff;
    #pragma unroll
    for (int nt = 0; nt < 16; nt++) {
        int code = c0 + nt*8 + 2*qid;
        float e2a = g_en2[code], e2b = g_en2[code+1];
        topk_insert(e2a - 2.f*acc[nt][0], code,   av0,ai0,av1,ai1,av2,ai2);
        topk_insert(e2b - 2.f*acc[nt][1], code+1, av0,ai0,av1,ai1,av2,ai2);
        topk_insert(e2a - 2.f*acc[nt][2], code,   bv0,bi0,bv1,bi1,bv2,bi2);
        topk_insert(e2b - 2.f*acc[nt][3], code+1, bv0,bi0,bv1,bi1,bv2,bi2);
    }
    #pragma unroll
    for (int off = 1; off <= 2; off <<= 1) {
        float t0 = __shfl_xor_sync(0xffffffffu, av0, off); int t0i = __shfl_xor_sync(0xffffffffu, ai0, off);
        float t1 = __shfl_xor_sync(0xffffffffu, av1, off); int t1i = __shfl_xor_sync(0xffffffffu, ai1, off);
        float t2 = __shfl_xor_sync(0xffffffffu, av2, off); int t2i = __shfl_xor_sync(0xffffffffu, ai2, off);
        topk_insert(t0, t0i, av0,ai0,av1,ai1,av2,ai2);
        topk_insert(t1, t1i, av0,ai0,av1,ai1,av2,ai2);
        topk_insert(t2, t2i, av0,ai0,av1,ai1,av2,ai2);
        float u0 = __shfl_xor_sync(0xffffffffu, bv0, off); int u0i = __shfl_xor_sync(0xffffffffu, bi0, off);
        float u1 = __shfl_xor_sync(0xffffffffu, bv1, off); int u1i = __shfl_xor_sync(0xffffffffu, bi1, off);
        float u2 = __shfl_xor_sync(0xffffffffu, bv2, off); int u2i = __shfl_xor_sync(0xffffffffu, bi2, off);
        topk_insert(u0, u0i, bv0,bi0,bv1,bi1,bv2,bi2);
        topk_insert(u1, u1i, bv0,bi0,bv1,bi1,bv2,bi2);
        topk_insert(u2, u2i, bv0,bi0,bv1,bi1,bv2,bi2);
    }
    if (qid == 0) {
        int rowA = r0 + m0 + grp;
        int baseA = rowA*24 + blockIdx.y*3;
        g_pv[baseA] = av0; g_pi[baseA] = ai0;
        g_pv[baseA+1] = av1; g_pi[baseA+1] = ai1;
        g_pv[baseA+2] = av2; g_pi[baseA+2] = ai2;
        int baseB = (rowA+8)*24 + blockIdx.y*3;
        g_pv[baseB] = bv0; g_pi[baseB] = bi0;
        g_pv[baseB+1] = bv1; g_pi[baseB+1] = bi1;
        g_pv[baseB+2] = bv2; g_pi[baseB+2] = bi2;
    }
}

// ---------------- top3 merge + counts ----------------
__global__ void top3_merge_kernel(int n0) {
    int n = n0 + blockIdx.y;
    int t = n*HW2 + blockIdx.x*256 + threadIdx.x;
    float v0 = 3.402823466e38f, v1 = v0, v2 = v0;
    int i0 = 0x7fffffff, i1 = 0x7fffffff, i2 = 0x7fffffff;
    #pragma unroll
    for (int j = 0; j < 24; j++)
        topk_insert(g_pv[t*24+j], g_pi[t*24+j], v0,i0,v1,i1,v2,i2);
    g_idx0[t] = i0;
    atomicAdd(&g_counts[i2], 1);
}

// ---------------- loss ----------------
__global__ void loss_part_kernel(const float* __restrict__ emb, const float* __restrict__ z,
                                 int n0) {
    int n = n0 + blockIdx.y;
    int p = blockIdx.x*256 + threadIdx.x;
    int row = n*HW2 + p;
    const float* e = emb + (size_t)g_idx0[row]*CCH;
    float s = 0.f;
    for (int d = 0; d < CCH; d++) {
        float zv = z[((size_t)(n*CCH + d))*HW2 + p];
        float df = e[d] - zv; s += df*df;
    }
    __shared__ float sh[256];
    sh[threadIdx.x] = s; __syncthreads();
    for (int o = 128; o; o >>= 1) { if (threadIdx.x < o) sh[threadIdx.x] += sh[threadIdx.x+o]; __syncthreads(); }
    if (threadIdx.x == 0) g_losspart[n*9 + blockIdx.x] = sh[0];
}

// ---------------- finalize ----------------
__global__ void finalize_kernel(float* out0, float* outp) {
    __shared__ float sh[1024];
    int t = threadIdx.x;
    float p = (float)g_counts[t] / (float)ROWS;
    sh[t] = p * logf(p + 1e-10f);
    __syncthreads();
    for (int o = 512; o; o >>= 1) { if (t < o) sh[t] += sh[t+o]; __syncthreads(); }
    if (t == 0) {
        outp[0] = expf(-sh[0]);
        float s = 0.f;
        for (int bb = 0; bb < 36; bb++) s += g_losspart[bb];
        out0[0] = 0.25f * s / ((float)ROWS * (float)CCH);
    }
}

// ---------------- d0: transpose conv parity streams, pipelined ----------------
#define D0_SMEM_FLOATS (16*168 + 9*16*40)
#define D0_STREAM(tap, cls, ro, sh)                                          \
    {                                                                        \
        int wb = (tap)*640 + (ks*8 + qid)*40 + m0 + grp;                     \
        float a0 = ws[wb],     a1 = ws[wb+8];                                \
        float a2 = ws[wb+160], a3 = ws[wb+168];                              \
        int bb = (ks*8 + qid)*168 + (sub + (ro))*56 + (sh) + half*24 + grp;  \
        _Pragma("unroll")                                                    \
        for (int nt = 0; nt < 3; nt++) {                                     \
            float b0 = inp[bb + nt*8];                                       \
            float b1 = inp[bb + 672 + nt*8];                                 \
            mma_tf32(acc[cls][nt], a0, a1, a2, a3, b0, b1);                  \
        }                                                                    \
    }
__global__ void __launch_bounds__(256) conv_d0_mma_kernel(
        const float* __restrict__ bias, float* __restrict__ out, int n0) {
    extern __shared__ float smem[];
    float* inp = smem;
    float* ws  = smem + 16*168;
    int n = n0 + blockIdx.z;
    int i0 = blockIdx.x*2, cb = blockIdx.y*32;
    int tid = threadIdx.x, lane = tid & 31, wid = tid >> 5;
    int sub = (wid >> 2) & 1, m0 = ((wid >> 1) & 1)*16, half = wid & 1;
    int grp = lane >> 2, qid = lane & 3;
    float acc[4][3][4];
    #pragma unroll
    for (int c = 0; c < 4; c++)
        #pragma unroll
        for (int i = 0; i < 3; i++)
            #pragma unroll
            for (int j = 0; j < 4; j++) acc[c][i][j] = 0.f;

    const float4 zero4 = make_float4(0.f, 0.f, 0.f, 0.f);
    for (int j = tid; j < 16*3*13; j += 256) {
        int ci = j/39, r = j%39, y = r/13, q = r%13;
        int ih = i0 + y;
        float4 v = zero4;
        if (ih < HH2)
            v = ((const float4*)g_qpack)[((size_t)((n*CCH + ci)*HH2 + ih))*13 + q];
        *(float4*)&inp[ci*168 + y*56 + q*4] = v;
    }
    #pragma unroll
    for (int it = 0; it < 18; it++) {
        int tap = it >> 1;
        int r = ((it & 1) << 8) + tid;
        int ci = r >> 5, co = r & 31;
        ws[tap*640 + ci*40 + co] = g_wd0[((size_t)(tap*128 + ci))*128 + cb + co];
    }
    __syncthreads();

    for (int c0 = 0; c0 < 128; c0 += 16) {
        float4 pv4[3];
        float pw[18];
        bool nx = (c0 < 112);
        if (nx) {
            int cn = c0 + 16;
            #pragma unroll
            for (int it = 0; it < 3; it++) {
                int j = tid + it*256;
                pv4[it] = zero4;
                if (j < 624) {
                    int ci = j/39, r = j%39, y = r/13, q = r%13;
                    int ih = i0 + y;
                    if (ih < HH2)
                        pv4[it] = ((const float4*)g_qpack)[((size_t)((n*CCH + cn+ci)*HH2 + ih))*13 + q];
                }
            }
            #pragma unroll
            for (int it = 0; it < 18; it++) {
                int tap = it >> 1;
                int r = ((it & 1) << 8) + tid;
                int ci = r >> 5, co = r & 31;
                pw[it] = g_wd0[((size_t)(tap*128 + cn+ci))*128 + cb + co];
            }
        }
        #pragma unroll
        for (int ks = 0; ks < 2; ks++) {
            D0_STREAM(4, 0, 0, 0)
            D0_STREAM(3, 1, 0, 1)
            D0_STREAM(5, 1, 0, 0)
            D0_STREAM(1, 2, 1, 0)
            D0_STREAM(7, 2, 0, 0)
            D0_STREAM(0, 3, 1, 1)
            D0_STREAM(2, 3, 1, 0)
            D0_STREAM(6, 3, 0, 1)
            D0_STREAM(8, 3, 0, 0)
        }
        __syncthreads();
        if (nx) {
            #pragma unroll
            for (int it = 0; it < 3; it++) {
                int j = tid + it*256;
                if (j < 624) {
                    int ci = j/39, r = j%39, y = r/13, q = r%13;
                    *(float4*)&inp[ci*168 + y*56 + q*4] = pv4[it];
                }
            }
            #pragma unroll
            for (int it = 0; it < 18; it++) {
                int tap = it >> 1;
                int r = ((it & 1) << 8) + tid;
                int ci = r >> 5, co = r & 31;
                ws[tap*640 + ci*40 + co] = pw[it];
            }
            __syncthreads();
        }
    }
    int i = i0 + sub;
    int coA = cb + m0 + grp, coB = coA + 8;
    float bA = bias[coA], bB = bias[coB];
    float* pA = out + ((size_t)(n*CCH + coA))*HWX + (2*i)*WWW;
    float* pB = out + ((size_t)(n*CCH + coB))*HWX + (2*i)*WWW;
    #pragma unroll
    for (int nt = 0; nt < 3; nt++) {
        int j = half*24 + nt*8 + 2*qid;
        pA[2*j]       = acc[0][nt][0] + bA;  pA[2*j+1]     = acc[1][nt][0] + bA;
        pA[2*j+2]     = acc[0][nt][1] + bA;  pA[2*j+3]     = acc[1][nt][1] + bA;
        pA[WWW+2*j]   = acc[2][nt][0] + bA;  pA[WWW+2*j+1] = acc[3][nt][0] + bA;
        pA[WWW+2*j+2] = acc[2][nt][1] + bA;  pA[WWW+2*j+3] = acc[3][nt][1] + bA;
        pB[2*j]       = acc[0][nt][2] + bB;  pB[2*j+1]     = acc[1][nt][2] + bB;
        pB[2*j+2]     = acc[0][nt][3] + bB;  pB[2*j+3]     = acc[1][nt][3] + bB;
        pB[WWW+2*j]   = acc[2][nt][2] + bB;  pB[WWW+2*j+1] = acc[3][nt][2] + bB;
        pB[WWW+2*j+2] = acc[2][nt][3] + bB;  pB[WWW+2*j+3] = acc[3][nt][3] + bB;
    }
}

// ---------------- d1: tf32 MMA, pipelined ----------------
#define D1_SMEM_FLOATS (16*424 + 9*16*40)
__global__ void __launch_bounds__(256) conv_d1_mma_kernel(
        const float* __restrict__ wpack, const float* __restrict__ bias,
        float* __restrict__ out, int n0) {
    extern __shared__ float smem[];
    float* inh = smem;
    float* wsh = smem + 16*424;
    int n = n0 + blockIdx.z;
    int oh0 = blockIdx.x*2, cb = blockIdx.y*32;
    int tid = threadIdx.x, lane = tid & 31, wid = tid >> 5;
    int row = (wid >> 2) & 1, m0 = ((wid >> 1) & 1)*16, half = wid & 1;
    int grp = lane >> 2, qid = lane & 3;
    float acc[6][4];
    #pragma unroll
    for (int i = 0; i < 6; i++)
        #pragma unroll
        for (int j = 0; j < 4; j++) acc[i][j] = 0.f;

    const float4 zero4 = make_float4(0.f, 0.f, 0.f, 0.f);
    for (int j = tid; j < 16*4*26; j += 256) {
        int ci = j/104, r = j%104, y = r/26, q = r%26;
        int ih = oh0 - 1 + y;
        float4 v = zero4;
        if (ih >= 0 && ih < 96)
            v = ((const float4*)g_dcomb)[((size_t)((n*256 + ci)*96 + ih))*26 + q];
        *(float4*)&inh[ci*424 + y*104 + q*4] = v;
    }
    #pragma unroll
    for (int it = 0; it < 18; it++) {
        int tap = it >> 1;
        int r = ((it & 1) << 8) + tid;
        int ci = r >> 5, co = r & 31;
        wsh[tap*640 + ci*40 + co] = wpack[((size_t)(tap*256 + ci))*128 + cb + co];
    }
    __syncthreads();

    for (int c0 = 0; c0 < 256; c0 += 16) {
        float4 pv4[7];
        float pw[18];
        bool nx = (c0 < 240);
        if (nx) {
            int cn = c0 + 16;
            #pragma unroll
            for (int it = 0; it < 7; it++) {
                int j = tid + it*256;
                pv4[it] = zero4;
                if (j < 1664) {
                    int ci = j/104, r = j%104, y = r/26, q = r%26;
                    int ih = oh0 - 1 + y;
                    if (ih >= 0 && ih < 96)
                        pv4[it] = ((const float4*)g_dcomb)[((size_t)((n*256 + cn+ci)*96 + ih))*26 + q];
                }
            }
            #pragma unroll
            for (int it = 0; it < 18; it++) {
                int tap = it >> 1;
                int r = ((it & 1) << 8) + tid;
                int ci = r >> 5, co = r & 31;
                pw[it] = wpack[((size_t)(tap*256 + cn+ci))*128 + cb + co];
            }
        }
        #pragma unroll
        for (int kh = 0; kh < 3; kh++) {
            #pragma unroll
            for (int kw = 0; kw < 3; kw++) {
                int tap = kh*3 + kw;
                #pragma unroll
                for (int ks = 0; ks < 2; ks++) {
                    int wb = tap*640 + (ks*8 + qid)*40 + m0 + grp;
                    float a0 = wsh[wb],     a1 = wsh[wb+8];
                    float a2 = wsh[wb+160], a3 = wsh[wb+168];
                    int bb = (ks*8 + qid)*424 + (row + kh)*104 + kw + half*48 + grp;
                    #pragma unroll
                    for (int nt = 0; nt < 6; nt++) {
                        float b0 = inh[bb + nt*8];
                        float b1 = inh[bb + 1696 + nt*8];
                        mma_tf32(acc[nt], a0, a1, a2, a3, b0, b1);
                    }
                }
            }
        }
        __syncthreads();
        if (nx) {
            #pragma unroll
            for (int it = 0; it < 7; it++) {
                int j = tid + it*256;
                if (j < 1664) {
                    int ci = j/104, r = j%104, y = r/26, q = r%26;
                    *(float4*)&inh[ci*424 + y*104 + q*4] = pv4[it];
                }
            }
            #pragma unroll
            for (int it = 0; it < 18; it++) {
                int tap = it >> 1;
                int r = ((it & 1) << 8) + tid;
                int ci = r >> 5, co = r & 31;
                wsh[tap*640 + ci*40 + co] = pw[it];
            }
            __syncthreads();
        }
    }
    int coA = cb + m0 + grp, coB = coA + 8;
    float bA = bias[coA], bB = bias[coB];
    int oh = oh0 + row;
    float* pA = out + ((size_t)(n*CCH + coA))*HWX + oh*WWW;
    float* pB = out + ((size_t)(n*CCH + coB))*HWX + oh*WWW;
    #pragma unroll
    for (int nt = 0; nt < 6; nt++) {
        int px = half*48 + nt*8 + 2*qid;
        pA[px]   = acc[nt][0] + bA;
        pA[px+1] = acc[nt][1] + bA;
        pB[px]   = acc[nt][2] + bB;
        pB[px+1] = acc[nt][3] + bB;
    }
}

// ---------------- ro: 1x1 128->4, fused d1-GN ----------------
__global__ void conv_ro_kernel(const float* __restrict__ y, const float* __restrict__ w,
                               const float* __restrict__ b, float* __restrict__ out,
                               const float* __restrict__ gam, const float* __restrict__ bet,
                               int n0) {
    int n = n0 + blockIdx.y;
    int p = blockIdx.x*256 + threadIdx.x;
    __shared__ float ws[512];
    __shared__ float As[128], Bs[128];
    for (int j = threadIdx.x; j < 512; j += 256) ws[j] = w[j];
    if (threadIdx.x < 128) {
        int c = threadIdx.x;
        int ng = n*2 + (c >> 6);
        float mu = g_stats2[3][ng][0], rs = g_stats2[3][ng][1];
        float gm = gam[c];
        As[c] = rs*gm;
        Bs[c] = bet[c] - mu*rs*gm;
    }
    __syncthreads();
    float a0 = b[0], a1 = b[1], a2 = b[2], a3 = b[3];
    const float* yp = y + (size_t)n*CCH*HWX + p;
    for (int ci = 0; ci < 128; ci++) {
        float v = yp[(size_t)ci*HWX];
        v = fmaf(v, As[ci], Bs[ci]);
        v = v >= 0.f ? v : SLOPE_F*v;
        a0 += v*ws[ci]; a1 += v*ws[128+ci]; a2 += v*ws[256+ci]; a3 += v*ws[384+ci];
    }
    out[((size_t)n*4 + 0)*HWX + p] = a0;
    out[((size_t)n*4 + 1)*HWX + p] = a1;
    out[((size_t)n*4 + 2)*HWX + p] = a2;
    out[((size_t)n*4 + 3)*HWX + p] = a3;
}

// ---------------- host ----------------
extern "C" void kernel_launch(void* const* d_in, const int* in_sizes, int n_in,
                              void* d_out, int out_size) {
    const float* x       = (const float*)d_in[0];
    const float* e0_w    = (const float*)d_in[1];
    const float* e0_b    = (const float*)d_in[2];
    const float* e0_g    = (const float*)d_in[3];
    const float* e0_beta = (const float*)d_in[4];
    const float* e1_w    = (const float*)d_in[5];
    const float* e1_b    = (const float*)d_in[6];
    const float* e1_g    = (const float*)d_in[7];
    const float* e1_beta = (const float*)d_in[8];
    const float* pv_w    = (const float*)d_in[9];
    const float* pv_b    = (const float*)d_in[10];
    const float* emb     = (const float*)d_in[11];
    const float* d0_w    = (const float*)d_in[12];
    const float* d0_b    = (const float*)d_in[13];
    const float* d0_g    = (const float*)d_in[14];
    const float* d0_beta = (const float*)d_in[15];
    const float* d1_w    = (const float*)d_in[16];
    const float* d1_b    = (const float*)d_in[17];
    const float* d1_g    = (const float*)d_in[18];
    const float* d1_beta = (const float*)d_in[19];
    const float* proj_w  = (const float*)d_in[20];
    const float* proj_b  = (const float*)d_in[21];
    const float* ro_w    = (const float*)d_in[22];
    const float* ro_b    = (const float*)d_in[23];
    float* out = (float*)d_out;

    float *bufA, *bufB, *zb, *hb, *yb, *wpk;
    cudaGetSymbolAddress((void**)&bufA, g_bufA);
    cudaGetSymbolAddress((void**)&bufB, g_bufB);
    cudaGetSymbolAddress((void**)&zb,   g_z);
    cudaGetSymbolAddress((void**)&hb,   g_h);
    cudaGetSymbolAddress((void**)&yb,   g_y);
    cudaGetSymbolAddress((void**)&wpk,  g_wpack);

    static cudaStream_t sP[2] = {nullptr, nullptr};
    static cudaEvent_t evInit = nullptr, evDone[2] = {nullptr, nullptr};
    if (sP[0] == nullptr) {
        for (int i = 0; i < 2; i++) {
            cudaStreamCreateWithFlags(&sP[i], cudaStreamNonBlocking);
            cudaEventCreateWithFlags(&evDone[i], cudaEventDisableTiming);
        }
        cudaEventCreateWithFlags(&evInit, cudaEventDisableTiming);
        cudaFuncSetAttribute(conv_e1_mma_kernel, cudaFuncAttributeMaxDynamicSharedMemorySize,
                             E1_SMEM_FLOATS*4);
        cudaFuncSetAttribute(conv_d0_mma_kernel, cudaFuncAttributeMaxDynamicSharedMemorySize,
                             D0_SMEM_FLOATS*4);
        cudaFuncSetAttribute(conv_d1_mma_kernel, cudaFuncAttributeMaxDynamicSharedMemorySize,
                             D1_SMEM_FLOATS*4);
    }

    // head on default stream
    init_pack_kernel<<<(9*256*128+255)/256, 256>>>(d1_w, d0_w, e1_w);
    enorm_kernel<<<CODES/8, 256>>>(emb);
    cudaEventRecord(evInit, 0);

    // 2 pipelines x 2 images each
    for (int pidx = 0; pidx < 2; pidx++) {
        int n0 = pidx*2;
        cudaStream_t s = sP[pidx];
        cudaStreamWaitEvent(s, evInit, 0);
        conv_e0_kernel<<<dim3(48,2,2), 192, 0, s>>>(x, e0_w, e0_b, bufA, n0);
        gn_part_kernel<<<dim3(2,64,2), 256, 0, s>>>(bufA, HWX, 0, n0);
        prep_e1_kernel<<<dim3(1536,2), 256, 0, s>>>(bufA, e0_g, e0_beta, n0);
        skip_mma_kernel<<<dim3(96,2), 256, 0, s>>>(bufA, proj_w, proj_b, e0_g, e0_beta, n0);
        conv_e1_mma_kernel<<<dim3(24,4,2), 256, E1_SMEM_FLOATS*4, s>>>(e1_b, bufB, n0);
        gn_part_kernel<<<dim3(2,64,2), 256, 0, s>>>(bufB, HW2, 1, n0);
        pv_mma_kernel<<<dim3(24,2,2), 256, 0, s>>>(bufB, pv_w, pv_b, e1_g, e1_beta, zb, n0);
        scores_mma_kernel<<<dim3(18,8,2), 256, 0, s>>>(emb, zb, n0);
        top3_merge_kernel<<<dim3(9,2), 256, 0, s>>>(n0);
        loss_part_kernel<<<dim3(9,2), 256, 0, s>>>(emb, zb, n0);
        prep_q_kernel<<<dim3(768,2), 256, 0, s>>>(emb, n0);
        conv_d0_mma_kernel<<<dim3(24,4,2), 256, D0_SMEM_FLOATS*4, s>>>(d0_b, hb, n0);
        gn_part_kernel<<<dim3(2,64,2), 256, 0, s>>>(hb, HWX, 2, n0);
        prep_d_kernel<<<dim3(1536,2), 256, 0, s>>>(hb, d0_g, d0_beta, n0);
        conv_d1_mma_kernel<<<dim3(48,4,2), 256, D1_SMEM_FLOATS*4, s>>>(wpk, d1_b, yb, n0);
        gn_part_kernel<<<dim3(2,64,2), 256, 0, s>>>(yb, HWX, 3, n0);
        conv_ro_kernel<<<dim3(36,2), 256, 0, s>>>(yb, ro_w, ro_b, out + 1, d1_g, d1_beta, n0);
        cudaEventRecord(evDone[pidx], s);
    }

    // join: finalize loss + perplexity
    cudaStreamWaitEvent(0, evDone[0], 0);
    cudaStreamWaitEvent(0, evDone[1], 0);
    finalize_kernel<<<1, 1024>>>(out, out + (out_size - 1));
}